// round 4
// baseline (speedup 1.0000x reference)
#include <cuda_runtime.h>
#include <math.h>

#define NN 100000
#define NE 1600000

// ---------------- scratch (device globals; no allocation allowed) ----------------
__device__ float g_xW1[NN * 64];
__device__ float g_al_s1[NN * 8];
__device__ float g_al_d1[NN * 8];
__device__ float g_h1[NN * 64];
__device__ float g_xW2[NN * 64];
__device__ float g_al_s2[NN];
__device__ float g_al_d2[NN];
__device__ float g_h2[NN * 64];
__device__ float g_P[NN * 128];
__device__ float g_Q[NN * 128];
__device__ float g_Wla[64 * 128];
__device__ float g_Wlb[64 * 128];
__device__ float g_bP[128];
__device__ float g_bQ[128];
__device__ int   g_deg[NN];
__device__ int   g_cursor[NN];
__device__ int   g_scantmp[NN];
__device__ int   g_rowptr[NN + 1];
__device__ int   g_bsum[128];
__device__ int   g_col[NE];
__device__ int   g_eid[NE];

// ---------------- GEMM: C[nrows,BN] = A[nrows,K] @ B[K,BN] (+bias)
// ALH: 0 = plain, 8 = fused 8-head attention logits, 1 = fused 1-head logits
template <int K, int BN, int TN, int ALH>
__global__ void __launch_bounds__(256)
k_gemm(const float* __restrict__ A, const float* __restrict__ B, int ldb,
       const float* __restrict__ bias, float* __restrict__ C, int nrows,
       const float* __restrict__ a_src, const float* __restrict__ a_dst,
       float* __restrict__ al_s, float* __restrict__ al_d)
{
    constexpr int BM = 64, KC = 16, PAD = 68;
    __shared__ float sB[K * BN];
    __shared__ float sA[KC * PAD];
    const int tid = threadIdx.x;
    const int tx = tid & 15, ty = tid >> 4;
    const int rowBase = blockIdx.x * BM;

    for (int i = tid; i < K * BN; i += 256)
        sB[i] = B[(i / BN) * ldb + (i % BN)];

    float acc[4][TN];
#pragma unroll
    for (int i = 0; i < 4; i++)
#pragma unroll
        for (int j = 0; j < TN; j++) acc[i][j] = 0.f;

    for (int kc = 0; kc < K; kc += KC) {
        __syncthreads();
        {
            int r = tid >> 2;
            int k4 = (tid & 3) << 2;
            int gr = rowBase + r;
            float4 av = make_float4(0.f, 0.f, 0.f, 0.f);
            if (gr < nrows) av = *(const float4*)(A + (long)gr * K + kc + k4);
            sA[(k4 + 0) * PAD + r] = av.x;
            sA[(k4 + 1) * PAD + r] = av.y;
            sA[(k4 + 2) * PAD + r] = av.z;
            sA[(k4 + 3) * PAD + r] = av.w;
        }
        __syncthreads();
#pragma unroll
        for (int kk = 0; kk < KC; kk++) {
            float4 a = *(const float4*)&sA[kk * PAD + 4 * ty];
            const float* bp = &sB[(kc + kk) * BN + 4 * tx];
            float av4[4] = {a.x, a.y, a.z, a.w};
            float bv[TN];
            float4 b0 = *(const float4*)bp;
            bv[0] = b0.x; bv[1] = b0.y; bv[2] = b0.z; bv[3] = b0.w;
            if (TN == 8) {
                float4 b1v = *(const float4*)(bp + 64);
                bv[4] = b1v.x; bv[5] = b1v.y; bv[6] = b1v.z; bv[7] = b1v.w;
            }
#pragma unroll
            for (int i = 0; i < 4; i++)
#pragma unroll
                for (int j = 0; j < TN; j++)
                    acc[i][j] = fmaf(av4[i], bv[j], acc[i][j]);
        }
    }

    float bb[TN];
#pragma unroll
    for (int j = 0; j < TN; j++) {
        int col = (j < 4) ? (4 * tx + j) : (64 + 4 * tx + (j - 4));
        bb[j] = bias ? bias[col] : 0.f;
    }
#pragma unroll
    for (int i = 0; i < 4; i++) {
        int r = rowBase + 4 * ty + i;
        if (r < nrows) {
            float4 o;
            o.x = acc[i][0] + bb[0]; o.y = acc[i][1] + bb[1];
            o.z = acc[i][2] + bb[2]; o.w = acc[i][3] + bb[3];
            *(float4*)(C + (long)r * BN + 4 * tx) = o;
            if (TN == 8) {
                float4 o2;
                o2.x = acc[i][4] + bb[4]; o2.y = acc[i][5] + bb[5];
                o2.z = acc[i][6] + bb[6]; o2.w = acc[i][7] + bb[7];
                *(float4*)(C + (long)r * BN + 64 + 4 * tx) = o2;
            }
        }
    }

    // fused attention-logit epilogue (BN==64 configs only)
    if (ALH > 0) {
        float as4[4], ad4[4];
#pragma unroll
        for (int j = 0; j < 4; j++) {
            as4[j] = a_src[4 * tx + j];
            ad4[j] = a_dst[4 * tx + j];
        }
#pragma unroll
        for (int i = 0; i < 4; i++) {
            float ps = 0.f, pd = 0.f;
#pragma unroll
            for (int j = 0; j < 4; j++) {
                ps = fmaf(acc[i][j], as4[j], ps);
                pd = fmaf(acc[i][j], ad4[j], pd);
            }
            int r = rowBase + 4 * ty + i;
            if (ALH == 8) {
                ps += __shfl_xor_sync(0xffffffffu, ps, 1);
                pd += __shfl_xor_sync(0xffffffffu, pd, 1);
                if (!(tx & 1) && r < nrows) {
                    al_s[(long)r * 8 + (tx >> 1)] = ps;
                    al_d[(long)r * 8 + (tx >> 1)] = pd;
                }
            } else {
#pragma unroll
                for (int off = 8; off >= 1; off >>= 1) {
                    ps += __shfl_xor_sync(0xffffffffu, ps, off);
                    pd += __shfl_xor_sync(0xffffffffu, pd, off);
                }
                if (tx == 0 && r < nrows) { al_s[r] = ps; al_d[r] = pd; }
            }
        }
    }
}

// ---------------- CSR build ----------------
__global__ void k_zero()
{
    int i = blockIdx.x * blockDim.x + threadIdx.x;
    if (i < NN) g_deg[i] = 0;
}
__global__ void k_hist(const int* __restrict__ ei)
{
    int e = blockIdx.x * blockDim.x + threadIdx.x;
    if (e < NE) atomicAdd(&g_deg[ei[NE + e]], 1);
}
__global__ void k_scan1()
{
    __shared__ int s[256];
    int tid = threadIdx.x;
    int base = blockIdx.x * 1024 + tid * 4;
    int v0 = (base + 0 < NN) ? g_deg[base + 0] : 0;
    int v1 = (base + 1 < NN) ? g_deg[base + 1] : 0;
    int v2 = (base + 2 < NN) ? g_deg[base + 2] : 0;
    int v3 = (base + 3 < NN) ? g_deg[base + 3] : 0;
    v1 += v0; v2 += v1; v3 += v2;
    int tot = v3;
    s[tid] = tot;
    __syncthreads();
    for (int off = 1; off < 256; off <<= 1) {
        int x = (tid >= off) ? s[tid - off] : 0;
        __syncthreads();
        s[tid] += x;
        __syncthreads();
    }
    int excl = s[tid] - tot;
    if (base + 0 < NN) g_scantmp[base + 0] = v0 + excl;
    if (base + 1 < NN) g_scantmp[base + 1] = v1 + excl;
    if (base + 2 < NN) g_scantmp[base + 2] = v2 + excl;
    if (base + 3 < NN) g_scantmp[base + 3] = v3 + excl;
    if (tid == 255) g_bsum[blockIdx.x] = s[255];
}
__global__ void k_scan2()
{
    __shared__ int s[128];
    int tid = threadIdx.x;
    int nb = (NN + 1023) / 1024;
    int v = (tid < nb) ? g_bsum[tid] : 0;
    s[tid] = v;
    __syncthreads();
    for (int off = 1; off < 128; off <<= 1) {
        int x = (tid >= off) ? s[tid - off] : 0;
        __syncthreads();
        s[tid] += x;
        __syncthreads();
    }
    if (tid < nb) g_bsum[tid] = s[tid] - v;  // exclusive
}
__global__ void k_scan3()
{
    int i = blockIdx.x * blockDim.x + threadIdx.x;
    if (i > NN) return;
    int v = (i == 0) ? 0 : (g_scantmp[i - 1] + g_bsum[(i - 1) >> 10]);
    g_rowptr[i] = v;
    if (i < NN) g_cursor[i] = v;
}
__global__ void k_scatter(const int* __restrict__ ei)
{
    int e = blockIdx.x * blockDim.x + threadIdx.x;
    if (e >= NE) return;
    int dst = ei[NE + e];
    int pos = atomicAdd(&g_cursor[dst], 1);
    g_col[pos] = ei[e];
    g_eid[pos] = e;
}

// ---------------- GAT layer 1 aggregation (8 heads, shfl-free online softmax) ----------------
__global__ void __launch_bounds__(256)
k_gat1(const float* __restrict__ b1)
{
    int node = (blockIdx.x * blockDim.x + threadIdx.x) >> 5;
    int lane = threadIdx.x & 31;
    if (node >= NN) return;
    int hl = lane >> 2;                // head owning features {2*lane, 2*lane+1}
    float ald = g_al_d1[(long)node * 8 + hl];

    // self-loop initializes the online-softmax state
    float e0 = g_al_s1[(long)node * 8 + hl] + ald;
    e0 = (e0 > 0.f) ? e0 : 0.2f * e0;
    float m = e0, d = 1.f;
    float2 acc = *(const float2*)(g_xW1 + (long)node * 64 + 2 * lane);

    int beg = g_rowptr[node], end = g_rowptr[node + 1];
    for (int i = beg; i < end; i++) {
        int src = g_col[i];
        float ee = g_al_s1[(long)src * 8 + hl] + ald;
        ee = (ee > 0.f) ? ee : 0.2f * ee;
        float mo = m;
        m = fmaxf(m, ee);
        float scale = __expf(mo - m);
        float w = __expf(ee - m);
        d = d * scale + w;
        float2 xv = *(const float2*)(g_xW1 + (long)src * 64 + 2 * lane);
        acc.x = fmaf(w, xv.x, acc.x * scale);
        acc.y = fmaf(w, xv.y, acc.y * scale);
    }
    float2 o;
    o.x = acc.x / d + b1[2 * lane];
    o.y = acc.y / d + b1[2 * lane + 1];
    o.x = (o.x > 0.f) ? o.x : expm1f(o.x);
    o.y = (o.y > 0.f) ? o.y : expm1f(o.y);
    *(float2*)(g_h1 + (long)node * 64 + 2 * lane) = o;
}

// ---------------- GAT layer 2 aggregation (1 head) ----------------
__global__ void __launch_bounds__(256)
k_gat2(const float* __restrict__ b2)
{
    int node = (blockIdx.x * blockDim.x + threadIdx.x) >> 5;
    int lane = threadIdx.x & 31;
    if (node >= NN) return;
    float ald = g_al_d2[node];
    float e0 = g_al_s2[node] + ald;
    e0 = (e0 > 0.f) ? e0 : 0.2f * e0;
    float m = e0, d = 1.f;
    float2 acc = *(const float2*)(g_xW2 + (long)node * 64 + 2 * lane);

    int beg = g_rowptr[node], end = g_rowptr[node + 1];
    for (int i = beg; i < end; i++) {
        int src = g_col[i];
        float ee = g_al_s2[src] + ald;
        ee = (ee > 0.f) ? ee : 0.2f * ee;
        float mo = m;
        m = fmaxf(m, ee);
        float scale = __expf(mo - m);
        float w = __expf(ee - m);
        d = d * scale + w;
        float2 xv = *(const float2*)(g_xW2 + (long)src * 64 + 2 * lane);
        acc.x = fmaf(w, xv.x, acc.x * scale);
        acc.y = fmaf(w, xv.y, acc.y * scale);
    }
    float2 o;
    o.x = acc.x / d + b2[2 * lane];
    o.y = acc.y / d + b2[2 * lane + 1];
    o.x = (o.x > 0.f) ? o.x : expm1f(o.x);
    o.y = (o.y > 0.f) ? o.y : expm1f(o.y);
    *(float2*)(g_h2 + (long)node * 64 + 2 * lane) = o;
}

// ---------------- fold lin_W (+bias) into mlp_W1 halves ----------------
__global__ void k_fold(const float* __restrict__ linW, const float* __restrict__ linb,
                       const float* __restrict__ mW1)
{
    int b = blockIdx.x;           // 129 blocks
    int c = threadIdx.x;          // 128 threads
    if (b < 128) {
        int i = b & 63;
        int off = (b >> 6) ? 64 : 0;
        float s = 0.f;
        for (int j = 0; j < 64; j++)
            s = fmaf(linW[i * 64 + j], mW1[(off + j) * 128 + c], s);
        ((b >> 6) ? g_Wlb : g_Wla)[i * 128 + c] = s;
    } else {
        float s0 = 0.f, s1 = 0.f;
        for (int j = 0; j < 64; j++) {
            s0 = fmaf(linb[j], mW1[j * 128 + c], s0);
            s1 = fmaf(linb[j], mW1[(64 + j) * 128 + c], s1);
        }
        g_bP[c] = s0;
        g_bQ[c] = s1;
    }
}

// ---------------- edge MLP + log_softmax (dst-ordered, warp per node) ----------------
__global__ void __launch_bounds__(256, 2)
k_edge(const int* __restrict__ ei, const float* __restrict__ ea,
       const float* __restrict__ mW1, const float* __restrict__ mb1,
       const float* __restrict__ mW2, const float* __restrict__ mb2,
       float* __restrict__ out)
{
    int lane = threadIdx.x & 31;
    int node = (blockIdx.x * blockDim.x + threadIdx.x) >> 5;
    if (node >= NN) return;

    float wc[16][4];
#pragma unroll
    for (int k = 0; k < 16; k++) {
        float4 v = *(const float4*)(mW1 + (long)(128 + k) * 128 + 4 * lane);
        wc[k][0] = v.x; wc[k][1] = v.y; wc[k][2] = v.z; wc[k][3] = v.w;
    }
    float w2a[4], w2b[4], br[4];
#pragma unroll
    for (int u = 0; u < 4; u++) {
        int j = 4 * lane + u;
        w2a[u] = mW2[j * 2 + 0];
        w2b[u] = mW2[j * 2 + 1];
        br[u]  = mb1[j];
    }
    float b20 = mb2[0], b21 = mb2[1];

    // Q[dst] loaded once per node (16x reuse vs edge-order)
    float4 q = *(const float4*)(g_Q + (long)node * 128 + 4 * lane);
    float qb[4] = {q.x + br[0], q.y + br[1], q.z + br[2], q.w + br[3]};

    int beg = g_rowptr[node], end = g_rowptr[node + 1];
    for (int i = beg; i < end; i++) {
        int src = g_col[i];
        int eid = g_eid[i];
        float eal = (lane < 16) ? ea[(long)eid * 16 + lane] : 0.f;
        float4 p = *(const float4*)(g_P + (long)src * 128 + 4 * lane);
        float h[4] = {p.x + qb[0], p.y + qb[1], p.z + qb[2], p.w + qb[3]};
#pragma unroll
        for (int k = 0; k < 16; k++) {
            float ek = __shfl_sync(0xffffffffu, eal, k);
            h[0] = fmaf(ek, wc[k][0], h[0]);
            h[1] = fmaf(ek, wc[k][1], h[1]);
            h[2] = fmaf(ek, wc[k][2], h[2]);
            h[3] = fmaf(ek, wc[k][3], h[3]);
        }
        float s0 = 0.f, s1 = 0.f;
#pragma unroll
        for (int u = 0; u < 4; u++) {
            float hv = fmaxf(h[u], 0.f);
            s0 = fmaf(hv, w2a[u], s0);
            s1 = fmaf(hv, w2b[u], s1);
        }
#pragma unroll
        for (int off = 16; off >= 1; off >>= 1) {
            s0 += __shfl_xor_sync(0xffffffffu, s0, off);
            s1 += __shfl_xor_sync(0xffffffffu, s1, off);
        }
        if (lane == 0) {
            float o0 = s0 + b20, o1 = s1 + b21;
            float mx = fmaxf(o0, o1), mn = fminf(o0, o1);
            float l = mx + log1pf(expf(mn - mx));
            *(float2*)(out + (long)eid * 2) = make_float2(o0 - l, o1 - l);
        }
    }
}

// ---------------- host ----------------
extern "C" void kernel_launch(void* const* d_in, const int* in_sizes, int n_in,
                              void* d_out, int out_size)
{
    (void)in_sizes; (void)n_in; (void)out_size;
    const float* x    = (const float*)d_in[0];
    const int*   ei   = (const int*)d_in[1];
    const float* eatt = (const float*)d_in[2];
    const float* W1   = (const float*)d_in[3];
    const float* as1  = (const float*)d_in[4];
    const float* ad1  = (const float*)d_in[5];
    const float* b1   = (const float*)d_in[6];
    const float* W2   = (const float*)d_in[7];
    const float* as2  = (const float*)d_in[8];
    const float* ad2  = (const float*)d_in[9];
    const float* b2   = (const float*)d_in[10];
    const float* linW = (const float*)d_in[11];
    const float* linb = (const float*)d_in[12];
    const float* mW1  = (const float*)d_in[13];
    const float* mb1  = (const float*)d_in[14];
    const float* mW2  = (const float*)d_in[15];
    const float* mb2  = (const float*)d_in[16];
    float* out = (float*)d_out;

    void *p_xW1, *p_als1, *p_ald1, *p_h1, *p_xW2, *p_als2, *p_ald2, *p_h2;
    void *p_P, *p_Q, *p_Wla, *p_Wlb, *p_bP, *p_bQ;
    cudaGetSymbolAddress(&p_xW1, g_xW1);
    cudaGetSymbolAddress(&p_als1, g_al_s1);
    cudaGetSymbolAddress(&p_ald1, g_al_d1);
    cudaGetSymbolAddress(&p_h1, g_h1);
    cudaGetSymbolAddress(&p_xW2, g_xW2);
    cudaGetSymbolAddress(&p_als2, g_al_s2);
    cudaGetSymbolAddress(&p_ald2, g_al_d2);
    cudaGetSymbolAddress(&p_h2, g_h2);
    cudaGetSymbolAddress(&p_P, g_P);
    cudaGetSymbolAddress(&p_Q, g_Q);
    cudaGetSymbolAddress(&p_Wla, g_Wla);
    cudaGetSymbolAddress(&p_Wlb, g_Wlb);
    cudaGetSymbolAddress(&p_bP, g_bP);
    cudaGetSymbolAddress(&p_bQ, g_bQ);

    const int GEMM_BLOCKS = (NN + 63) / 64;       // 1563
    const int WARP_BLOCKS = (NN + 7) / 8;         // 12500 (warp per node)
    const int EDGE_BLOCKS = (NE + 255) / 256;     // 6250

    // CSR build (col + edge id, cursor pre-seeded by scan3)
    k_zero<<<(NN + 255) / 256, 256>>>();
    k_hist<<<EDGE_BLOCKS, 256>>>(ei);
    k_scan1<<<(NN + 1023) / 1024, 256>>>();
    k_scan2<<<1, 128>>>();
    k_scan3<<<(NN + 1 + 255) / 256, 256>>>();
    k_scatter<<<EDGE_BLOCKS, 256>>>(ei);

    // fold lin into mlp_W1 halves (graph-independent)
    k_fold<<<129, 128>>>(linW, linb, mW1);

    // GAT layer 1 (attention logits fused into GEMM epilogue)
    k_gemm<128, 64, 4, 8><<<GEMM_BLOCKS, 256>>>(x, W1, 64, nullptr, (float*)p_xW1, NN,
                                                as1, ad1, (float*)p_als1, (float*)p_ald1);
    k_gat1<<<WARP_BLOCKS, 256>>>(b1);

    // GAT layer 2
    k_gemm<64, 64, 4, 1><<<GEMM_BLOCKS, 256>>>((const float*)p_h1, W2, 64, nullptr,
                                               (float*)p_xW2, NN,
                                               as2, ad2, (float*)p_als2, (float*)p_ald2);
    k_gat2<<<WARP_BLOCKS, 256>>>(b2);

    // P = h2 @ (linW@W1a) + lin_b@W1a ; Q likewise for W1b
    k_gemm<64, 128, 8, 0><<<GEMM_BLOCKS, 256>>>((const float*)p_h2, (const float*)p_Wla, 128,
                                                (const float*)p_bP, (float*)p_P, NN,
                                                nullptr, nullptr, nullptr, nullptr);
    k_gemm<64, 128, 8, 0><<<GEMM_BLOCKS, 256>>>((const float*)p_h2, (const float*)p_Wlb, 128,
                                                (const float*)p_bQ, (float*)p_Q, NN,
                                                nullptr, nullptr, nullptr, nullptr);

    // edge MLP + log_softmax over dst-ordered CSR
    k_edge<<<WARP_BLOCKS, 256>>>(ei, eatt, mW1, mb1, mW2, mb2, out);
}

// round 5
// speedup vs baseline: 1.3943x; 1.3943x over previous
#include <cuda_runtime.h>
#include <math.h>

#define NN 100000
#define NE 1600000

// ---------------- scratch (device globals; no allocation allowed) ----------------
__device__ float g_xW1[NN * 64];
__device__ float g_al_s1[NN * 8];
__device__ float g_al_d1[NN * 8];
__device__ float g_h1[NN * 64];
__device__ float g_xW2[NN * 64];
__device__ float g_al_s2[NN];
__device__ float g_al_d2[NN];
__device__ float g_h2[NN * 64];
__device__ float g_P[NN * 128];
__device__ float g_Q[NN * 128];
__device__ float g_Wla[64 * 128];
__device__ float g_Wlb[64 * 128];
__device__ float g_bP[128];
__device__ float g_bQ[128];
__device__ int   g_deg[NN];
__device__ int   g_cursor[NN];
__device__ int   g_scantmp[NN];
__device__ int   g_rowptr[NN + 1];
__device__ int   g_bsum[128];
__device__ int   g_col[NE];

// ---------------- GEMM: C[nrows,BN] = A[nrows,K] @ B[K,BN] (+bias)
// ALH: 0 = plain, 8 = fused 8-head attention logits, 1 = fused 1-head logits
template <int K, int BN, int TN, int ALH>
__global__ void __launch_bounds__(256)
k_gemm(const float* __restrict__ A, const float* __restrict__ B, int ldb,
       const float* __restrict__ bias, float* __restrict__ C, int nrows,
       const float* __restrict__ a_src, const float* __restrict__ a_dst,
       float* __restrict__ al_s, float* __restrict__ al_d)
{
    constexpr int BM = 64, KC = 16, PAD = 68;
    __shared__ float sB[K * BN];
    __shared__ float sA[KC * PAD];
    const int tid = threadIdx.x;
    const int tx = tid & 15, ty = tid >> 4;
    const int rowBase = blockIdx.x * BM;

    for (int i = tid; i < K * BN; i += 256)
        sB[i] = B[(i / BN) * ldb + (i % BN)];

    float acc[4][TN];
#pragma unroll
    for (int i = 0; i < 4; i++)
#pragma unroll
        for (int j = 0; j < TN; j++) acc[i][j] = 0.f;

    for (int kc = 0; kc < K; kc += KC) {
        __syncthreads();
        {
            int r = tid >> 2;
            int k4 = (tid & 3) << 2;
            int gr = rowBase + r;
            float4 av = make_float4(0.f, 0.f, 0.f, 0.f);
            if (gr < nrows) av = *(const float4*)(A + (long)gr * K + kc + k4);
            sA[(k4 + 0) * PAD + r] = av.x;
            sA[(k4 + 1) * PAD + r] = av.y;
            sA[(k4 + 2) * PAD + r] = av.z;
            sA[(k4 + 3) * PAD + r] = av.w;
        }
        __syncthreads();
#pragma unroll
        for (int kk = 0; kk < KC; kk++) {
            float4 a = *(const float4*)&sA[kk * PAD + 4 * ty];
            const float* bp = &sB[(kc + kk) * BN + 4 * tx];
            float av4[4] = {a.x, a.y, a.z, a.w};
            float bv[TN];
            float4 b0 = *(const float4*)bp;
            bv[0] = b0.x; bv[1] = b0.y; bv[2] = b0.z; bv[3] = b0.w;
            if (TN == 8) {
                float4 b1v = *(const float4*)(bp + 64);
                bv[4] = b1v.x; bv[5] = b1v.y; bv[6] = b1v.z; bv[7] = b1v.w;
            }
#pragma unroll
            for (int i = 0; i < 4; i++)
#pragma unroll
                for (int j = 0; j < TN; j++)
                    acc[i][j] = fmaf(av4[i], bv[j], acc[i][j]);
        }
    }

    float bb[TN];
#pragma unroll
    for (int j = 0; j < TN; j++) {
        int col = (j < 4) ? (4 * tx + j) : (64 + 4 * tx + (j - 4));
        bb[j] = bias ? bias[col] : 0.f;
    }
#pragma unroll
    for (int i = 0; i < 4; i++) {
        int r = rowBase + 4 * ty + i;
        if (r < nrows) {
            float4 o;
            o.x = acc[i][0] + bb[0]; o.y = acc[i][1] + bb[1];
            o.z = acc[i][2] + bb[2]; o.w = acc[i][3] + bb[3];
            *(float4*)(C + (long)r * BN + 4 * tx) = o;
            if (TN == 8) {
                float4 o2;
                o2.x = acc[i][4] + bb[4]; o2.y = acc[i][5] + bb[5];
                o2.z = acc[i][6] + bb[6]; o2.w = acc[i][7] + bb[7];
                *(float4*)(C + (long)r * BN + 64 + 4 * tx) = o2;
            }
        }
    }

    // fused attention-logit epilogue (BN==64 configs only)
    if (ALH > 0) {
        float as4[4], ad4[4];
#pragma unroll
        for (int j = 0; j < 4; j++) {
            as4[j] = a_src[4 * tx + j];
            ad4[j] = a_dst[4 * tx + j];
        }
#pragma unroll
        for (int i = 0; i < 4; i++) {
            float ps = 0.f, pd = 0.f;
#pragma unroll
            for (int j = 0; j < 4; j++) {
                ps = fmaf(acc[i][j], as4[j], ps);
                pd = fmaf(acc[i][j], ad4[j], pd);
            }
            int r = rowBase + 4 * ty + i;
            if (ALH == 8) {
                ps += __shfl_xor_sync(0xffffffffu, ps, 1);
                pd += __shfl_xor_sync(0xffffffffu, pd, 1);
                if (!(tx & 1) && r < nrows) {
                    al_s[(long)r * 8 + (tx >> 1)] = ps;
                    al_d[(long)r * 8 + (tx >> 1)] = pd;
                }
            } else {
#pragma unroll
                for (int off = 8; off >= 1; off >>= 1) {
                    ps += __shfl_xor_sync(0xffffffffu, ps, off);
                    pd += __shfl_xor_sync(0xffffffffu, pd, off);
                }
                if (tx == 0 && r < nrows) { al_s[r] = ps; al_d[r] = pd; }
            }
        }
    }
}

// ---------------- CSR build ----------------
__global__ void k_zero()
{
    int i = blockIdx.x * blockDim.x + threadIdx.x;
    if (i < NN) g_deg[i] = 0;
}
__global__ void k_hist(const int* __restrict__ ei)
{
    int e = blockIdx.x * blockDim.x + threadIdx.x;
    if (e < NE) atomicAdd(&g_deg[ei[NE + e]], 1);
}
__global__ void k_scan1()
{
    __shared__ int s[256];
    int tid = threadIdx.x;
    int base = blockIdx.x * 1024 + tid * 4;
    int v0 = (base + 0 < NN) ? g_deg[base + 0] : 0;
    int v1 = (base + 1 < NN) ? g_deg[base + 1] : 0;
    int v2 = (base + 2 < NN) ? g_deg[base + 2] : 0;
    int v3 = (base + 3 < NN) ? g_deg[base + 3] : 0;
    v1 += v0; v2 += v1; v3 += v2;
    int tot = v3;
    s[tid] = tot;
    __syncthreads();
    for (int off = 1; off < 256; off <<= 1) {
        int x = (tid >= off) ? s[tid - off] : 0;
        __syncthreads();
        s[tid] += x;
        __syncthreads();
    }
    int excl = s[tid] - tot;
    if (base + 0 < NN) g_scantmp[base + 0] = v0 + excl;
    if (base + 1 < NN) g_scantmp[base + 1] = v1 + excl;
    if (base + 2 < NN) g_scantmp[base + 2] = v2 + excl;
    if (base + 3 < NN) g_scantmp[base + 3] = v3 + excl;
    if (tid == 255) g_bsum[blockIdx.x] = s[255];
}
__global__ void k_scan2()
{
    __shared__ int s[128];
    int tid = threadIdx.x;
    int nb = (NN + 1023) / 1024;
    int v = (tid < nb) ? g_bsum[tid] : 0;
    s[tid] = v;
    __syncthreads();
    for (int off = 1; off < 128; off <<= 1) {
        int x = (tid >= off) ? s[tid - off] : 0;
        __syncthreads();
        s[tid] += x;
        __syncthreads();
    }
    if (tid < nb) g_bsum[tid] = s[tid] - v;  // exclusive
}
__global__ void k_scan3()
{
    int i = blockIdx.x * blockDim.x + threadIdx.x;
    if (i > NN) return;
    int v = (i == 0) ? 0 : (g_scantmp[i - 1] + g_bsum[(i - 1) >> 10]);
    g_rowptr[i] = v;
    if (i < NN) g_cursor[i] = v;
}
__global__ void k_scatter(const int* __restrict__ ei)
{
    int e = blockIdx.x * blockDim.x + threadIdx.x;
    if (e >= NE) return;
    int dst = ei[NE + e];
    int pos = atomicAdd(&g_cursor[dst], 1);
    g_col[pos] = ei[e];
}

// ---------------- GAT layer 1 aggregation (8 heads, shfl-free online softmax) ----------------
__global__ void __launch_bounds__(256)
k_gat1(const float* __restrict__ b1)
{
    int node = (blockIdx.x * blockDim.x + threadIdx.x) >> 5;
    int lane = threadIdx.x & 31;
    if (node >= NN) return;
    int hl = lane >> 2;                // head owning features {2*lane, 2*lane+1}
    float ald = g_al_d1[(long)node * 8 + hl];

    // self-loop initializes the online-softmax state
    float e0 = g_al_s1[(long)node * 8 + hl] + ald;
    e0 = (e0 > 0.f) ? e0 : 0.2f * e0;
    float m = e0, d = 1.f;
    float2 acc = *(const float2*)(g_xW1 + (long)node * 64 + 2 * lane);

    int beg = g_rowptr[node], end = g_rowptr[node + 1];
    for (int i = beg; i < end; i++) {
        int src = g_col[i];
        float ee = g_al_s1[(long)src * 8 + hl] + ald;
        ee = (ee > 0.f) ? ee : 0.2f * ee;
        float mo = m;
        m = fmaxf(m, ee);
        float scale = __expf(mo - m);
        float w = __expf(ee - m);
        d = d * scale + w;
        float2 xv = *(const float2*)(g_xW1 + (long)src * 64 + 2 * lane);
        acc.x = fmaf(w, xv.x, acc.x * scale);
        acc.y = fmaf(w, xv.y, acc.y * scale);
    }
    float2 o;
    o.x = acc.x / d + b1[2 * lane];
    o.y = acc.y / d + b1[2 * lane + 1];
    o.x = (o.x > 0.f) ? o.x : expm1f(o.x);
    o.y = (o.y > 0.f) ? o.y : expm1f(o.y);
    *(float2*)(g_h1 + (long)node * 64 + 2 * lane) = o;
}

// ---------------- GAT layer 2 aggregation (1 head) ----------------
__global__ void __launch_bounds__(256)
k_gat2(const float* __restrict__ b2)
{
    int node = (blockIdx.x * blockDim.x + threadIdx.x) >> 5;
    int lane = threadIdx.x & 31;
    if (node >= NN) return;
    float ald = g_al_d2[node];
    float e0 = g_al_s2[node] + ald;
    e0 = (e0 > 0.f) ? e0 : 0.2f * e0;
    float m = e0, d = 1.f;
    float2 acc = *(const float2*)(g_xW2 + (long)node * 64 + 2 * lane);

    int beg = g_rowptr[node], end = g_rowptr[node + 1];
    for (int i = beg; i < end; i++) {
        int src = g_col[i];
        float ee = g_al_s2[src] + ald;
        ee = (ee > 0.f) ? ee : 0.2f * ee;
        float mo = m;
        m = fmaxf(m, ee);
        float scale = __expf(mo - m);
        float w = __expf(ee - m);
        d = d * scale + w;
        float2 xv = *(const float2*)(g_xW2 + (long)src * 64 + 2 * lane);
        acc.x = fmaf(w, xv.x, acc.x * scale);
        acc.y = fmaf(w, xv.y, acc.y * scale);
    }
    float2 o;
    o.x = acc.x / d + b2[2 * lane];
    o.y = acc.y / d + b2[2 * lane + 1];
    o.x = (o.x > 0.f) ? o.x : expm1f(o.x);
    o.y = (o.y > 0.f) ? o.y : expm1f(o.y);
    *(float2*)(g_h2 + (long)node * 64 + 2 * lane) = o;
}

// ---------------- fold lin_W (+bias) into mlp_W1 halves ----------------
__global__ void k_fold(const float* __restrict__ linW, const float* __restrict__ linb,
                       const float* __restrict__ mW1)
{
    int b = blockIdx.x;           // 129 blocks
    int c = threadIdx.x;          // 128 threads
    if (b < 128) {
        int i = b & 63;
        int off = (b >> 6) ? 64 : 0;
        float s = 0.f;
        for (int j = 0; j < 64; j++)
            s = fmaf(linW[i * 64 + j], mW1[(off + j) * 128 + c], s);
        ((b >> 6) ? g_Wlb : g_Wla)[i * 128 + c] = s;
    } else {
        float s0 = 0.f, s1 = 0.f;
        for (int j = 0; j < 64; j++) {
            s0 = fmaf(linb[j], mW1[j * 128 + c], s0);
            s1 = fmaf(linb[j], mW1[(64 + j) * 128 + c], s1);
        }
        g_bP[c] = s0;
        g_bQ[c] = s1;
    }
}

// ---------------- edge MLP + log_softmax (edge-parallel: ea/out streamed) ----------------
__global__ void __launch_bounds__(256, 2)
k_edge(const int* __restrict__ ei, const float* __restrict__ ea,
       const float* __restrict__ mW1, const float* __restrict__ mb1,
       const float* __restrict__ mW2, const float* __restrict__ mb2,
       float* __restrict__ out)
{
    int lane = threadIdx.x & 31;
    int warp = (blockIdx.x * blockDim.x + threadIdx.x) >> 5;
    int nwarps = (gridDim.x * blockDim.x) >> 5;

    float wc[16][4];
#pragma unroll
    for (int k = 0; k < 16; k++) {
        float4 v = *(const float4*)(mW1 + (long)(128 + k) * 128 + 4 * lane);
        wc[k][0] = v.x; wc[k][1] = v.y; wc[k][2] = v.z; wc[k][3] = v.w;
    }
    float w2a[4], w2b[4], br[4];
#pragma unroll
    for (int u = 0; u < 4; u++) {
        int j = 4 * lane + u;
        w2a[u] = mW2[j * 2 + 0];
        w2b[u] = mW2[j * 2 + 1];
        br[u]  = mb1[j];
    }
    float b20 = mb2[0], b21 = mb2[1];

    for (int e = warp; e < NE; e += nwarps) {
        int src = ei[e];
        int dst = ei[NE + e];
        float eal = (lane < 16) ? ea[(long)e * 16 + lane] : 0.f;
        float4 p = *(const float4*)(g_P + (long)src * 128 + 4 * lane);
        float4 q = *(const float4*)(g_Q + (long)dst * 128 + 4 * lane);
        float h[4] = {p.x + q.x + br[0], p.y + q.y + br[1],
                      p.z + q.z + br[2], p.w + q.w + br[3]};
#pragma unroll
        for (int k = 0; k < 16; k++) {
            float ek = __shfl_sync(0xffffffffu, eal, k);
            h[0] = fmaf(ek, wc[k][0], h[0]);
            h[1] = fmaf(ek, wc[k][1], h[1]);
            h[2] = fmaf(ek, wc[k][2], h[2]);
            h[3] = fmaf(ek, wc[k][3], h[3]);
        }
        float s0 = 0.f, s1 = 0.f;
#pragma unroll
        for (int u = 0; u < 4; u++) {
            float hv = fmaxf(h[u], 0.f);
            s0 = fmaf(hv, w2a[u], s0);
            s1 = fmaf(hv, w2b[u], s1);
        }
#pragma unroll
        for (int off = 16; off >= 1; off >>= 1) {
            s0 += __shfl_xor_sync(0xffffffffu, s0, off);
            s1 += __shfl_xor_sync(0xffffffffu, s1, off);
        }
        if (lane == 0) {
            float o0 = s0 + b20, o1 = s1 + b21;
            float mx = fmaxf(o0, o1), mn = fminf(o0, o1);
            float l = mx + log1pf(expf(mn - mx));
            *(float2*)(out + (long)e * 2) = make_float2(o0 - l, o1 - l);
        }
    }
}

// ---------------- host ----------------
extern "C" void kernel_launch(void* const* d_in, const int* in_sizes, int n_in,
                              void* d_out, int out_size)
{
    (void)in_sizes; (void)n_in; (void)out_size;
    const float* x    = (const float*)d_in[0];
    const int*   ei   = (const int*)d_in[1];
    const float* eatt = (const float*)d_in[2];
    const float* W1   = (const float*)d_in[3];
    const float* as1  = (const float*)d_in[4];
    const float* ad1  = (const float*)d_in[5];
    const float* b1   = (const float*)d_in[6];
    const float* W2   = (const float*)d_in[7];
    const float* as2  = (const float*)d_in[8];
    const float* ad2  = (const float*)d_in[9];
    const float* b2   = (const float*)d_in[10];
    const float* linW = (const float*)d_in[11];
    const float* linb = (const float*)d_in[12];
    const float* mW1  = (const float*)d_in[13];
    const float* mb1  = (const float*)d_in[14];
    const float* mW2  = (const float*)d_in[15];
    const float* mb2  = (const float*)d_in[16];
    float* out = (float*)d_out;

    void *p_xW1, *p_als1, *p_ald1, *p_h1, *p_xW2, *p_als2, *p_ald2, *p_h2;
    void *p_P, *p_Q, *p_Wla, *p_Wlb, *p_bP, *p_bQ;
    cudaGetSymbolAddress(&p_xW1, g_xW1);
    cudaGetSymbolAddress(&p_als1, g_al_s1);
    cudaGetSymbolAddress(&p_ald1, g_al_d1);
    cudaGetSymbolAddress(&p_h1, g_h1);
    cudaGetSymbolAddress(&p_xW2, g_xW2);
    cudaGetSymbolAddress(&p_als2, g_al_s2);
    cudaGetSymbolAddress(&p_ald2, g_al_d2);
    cudaGetSymbolAddress(&p_h2, g_h2);
    cudaGetSymbolAddress(&p_P, g_P);
    cudaGetSymbolAddress(&p_Q, g_Q);
    cudaGetSymbolAddress(&p_Wla, g_Wla);
    cudaGetSymbolAddress(&p_Wlb, g_Wlb);
    cudaGetSymbolAddress(&p_bP, g_bP);
    cudaGetSymbolAddress(&p_bQ, g_bQ);

    const int GEMM_BLOCKS = (NN + 63) / 64;       // 1563
    const int WARP_BLOCKS = (NN + 7) / 8;         // 12500 (warp per node)
    const int EDGE_BLOCKS = (NE + 255) / 256;     // 6250

    // Launch order puts the big GEMM in the ncu-profiled slot (#4).
    k_zero<<<(NN + 255) / 256, 256>>>();
    k_hist<<<EDGE_BLOCKS, 256>>>(ei);
    k_scan1<<<(NN + 1023) / 1024, 256>>>();

    // GAT layer 1 projection + fused attention logits (independent of CSR)
    k_gemm<128, 64, 4, 8><<<GEMM_BLOCKS, 256>>>(x, W1, 64, nullptr, (float*)p_xW1, NN,
                                                as1, ad1, (float*)p_als1, (float*)p_ald1);

    k_scan2<<<1, 128>>>();
    k_scan3<<<(NN + 1 + 255) / 256, 256>>>();
    k_scatter<<<EDGE_BLOCKS, 256>>>(ei);

    // fold lin into mlp_W1 halves (graph-independent)
    k_fold<<<129, 128>>>(linW, linb, mW1);

    k_gat1<<<WARP_BLOCKS, 256>>>(b1);

    // GAT layer 2
    k_gemm<64, 64, 4, 1><<<GEMM_BLOCKS, 256>>>((const float*)p_h1, W2, 64, nullptr,
                                               (float*)p_xW2, NN,
                                               as2, ad2, (float*)p_als2, (float*)p_ald2);
    k_gat2<<<WARP_BLOCKS, 256>>>(b2);

    // P = h2 @ (linW@W1a) + lin_b@W1a ; Q likewise for W1b
    k_gemm<64, 128, 8, 0><<<GEMM_BLOCKS, 256>>>((const float*)p_h2, (const float*)p_Wla, 128,
                                                (const float*)p_bP, (float*)p_P, NN,
                                                nullptr, nullptr, nullptr, nullptr);
    k_gemm<64, 128, 8, 0><<<GEMM_BLOCKS, 256>>>((const float*)p_h2, (const float*)p_Wlb, 128,
                                                (const float*)p_bQ, (float*)p_Q, NN,
                                                nullptr, nullptr, nullptr, nullptr);

    // edge MLP + log_softmax (ea and out fully streamed; P/Q random but L2-resident)
    k_edge<<<2368, 256>>>(ei, eatt, mW1, mb1, mW2, mb2, out);
}

// round 7
// speedup vs baseline: 1.5320x; 1.0988x over previous
#include <cuda_runtime.h>
#include <math.h>

#define NN 100000
#define NE 1600000

typedef unsigned long long ull;

// ---------------- f32x2 packed math (sm_100+; ptxas never emits these from C++) ----
__device__ __forceinline__ ull pk2(float lo, float hi) {
    ull r; asm("mov.b64 %0, {%1, %2};" : "=l"(r) : "f"(lo), "f"(hi)); return r;
}
__device__ __forceinline__ void upk2(ull v, float& lo, float& hi) {
    asm("mov.b64 {%0, %1}, %2;" : "=f"(lo), "=f"(hi) : "l"(v));
}
__device__ __forceinline__ ull fma2(ull a, ull b, ull c) {
    ull d; asm("fma.rn.f32x2 %0, %1, %2, %3;" : "=l"(d) : "l"(a), "l"(b), "l"(c)); return d;
}
__device__ __forceinline__ ull add2(ull a, ull b) {
    ull d; asm("add.rn.f32x2 %0, %1, %2;" : "=l"(d) : "l"(a), "l"(b)); return d;
}
__device__ __forceinline__ ull mul2(ull a, ull b) {
    ull d; asm("mul.rn.f32x2 %0, %1, %2;" : "=l"(d) : "l"(a), "l"(b)); return d;
}

// ---------------- scratch (device globals; no allocation allowed) ----------------
__device__ float g_xW1[NN * 64];
__device__ float g_al_s1[NN * 8];
__device__ float g_al_d1[NN * 8];
__device__ float g_h1[NN * 64];
__device__ float g_xW2[NN * 64];
__device__ float g_al_s2[NN];
__device__ float g_al_d2[NN];
__device__ float g_h2[NN * 64];
__device__ float g_P[NN * 128];
__device__ float g_Q[NN * 128];
__device__ float g_Wla[64 * 128];
__device__ float g_Wlb[64 * 128];
__device__ float g_bP[128];
__device__ float g_bQ[128];
__device__ int   g_deg[NN];
__device__ int   g_cursor[NN];
__device__ int   g_scantmp[NN];
__device__ int   g_rowptr[NN + 1];
__device__ int   g_bsum[128];
__device__ int   g_col[NE];

// ---------------- GEMM: C[nrows,BN] = A[nrows,K] @ B[K,BN] (+bias)
// ALH: 0 = plain, 8 = fused 8-head attention logits, 1 = fused 1-head logits
template <int K, int BN, int TN, int ALH>
__global__ void __launch_bounds__(256)
k_gemm(const float* __restrict__ A, const float* __restrict__ B, int ldb,
       const float* __restrict__ bias, float* __restrict__ C, int nrows,
       const float* __restrict__ a_src, const float* __restrict__ a_dst,
       float* __restrict__ al_s, float* __restrict__ al_d)
{
    constexpr int BM = 64, KC = 16, PAD = 68;
    __shared__ __align__(16) float sB[K * BN];
    __shared__ __align__(16) float sA[KC * PAD];
    const int tid = threadIdx.x;
    const int tx = tid & 15, ty = tid >> 4;
    const int rowBase = blockIdx.x * BM;

    for (int i = tid; i < K * BN; i += 256)
        sB[i] = B[(i / BN) * ldb + (i % BN)];

    ull accp[4][TN / 2];
#pragma unroll
    for (int i = 0; i < 4; i++)
#pragma unroll
        for (int j = 0; j < TN / 2; j++) accp[i][j] = pk2(0.f, 0.f);

    for (int kc = 0; kc < K; kc += KC) {
        __syncthreads();
        {
            int r = tid >> 2;
            int k4 = (tid & 3) << 2;
            int gr = rowBase + r;
            float4 av = make_float4(0.f, 0.f, 0.f, 0.f);
            if (gr < nrows) av = *(const float4*)(A + (long)gr * K + kc + k4);
            sA[(k4 + 0) * PAD + r] = av.x;
            sA[(k4 + 1) * PAD + r] = av.y;
            sA[(k4 + 2) * PAD + r] = av.z;
            sA[(k4 + 3) * PAD + r] = av.w;
        }
        __syncthreads();
#pragma unroll
        for (int kk = 0; kk < KC; kk++) {
            float4 a = *(const float4*)&sA[kk * PAD + 4 * ty];
            ull bv[TN / 2];
            {
                ulonglong2 b2 = *(const ulonglong2*)&sB[(kc + kk) * BN + 4 * tx];
                bv[0] = b2.x; bv[1] = b2.y;
                if (TN == 8) {
                    ulonglong2 b3 = *(const ulonglong2*)&sB[(kc + kk) * BN + 64 + 4 * tx];
                    bv[2] = b3.x; bv[3] = b3.y;
                }
            }
            float av4[4] = {a.x, a.y, a.z, a.w};
#pragma unroll
            for (int i = 0; i < 4; i++) {
                ull ap = pk2(av4[i], av4[i]);
#pragma unroll
                for (int j = 0; j < TN / 2; j++)
                    accp[i][j] = fma2(ap, bv[j], accp[i][j]);
            }
        }
    }

    float acc[4][TN];
#pragma unroll
    for (int i = 0; i < 4; i++)
#pragma unroll
        for (int j = 0; j < TN / 2; j++)
            upk2(accp[i][j], acc[i][2 * j], acc[i][2 * j + 1]);

    float bb[TN];
#pragma unroll
    for (int j = 0; j < TN; j++) {
        int col = (j < 4) ? (4 * tx + j) : (64 + 4 * tx + (j - 4));
        bb[j] = bias ? bias[col] : 0.f;
    }
#pragma unroll
    for (int i = 0; i < 4; i++) {
        int r = rowBase + 4 * ty + i;
        if (r < nrows) {
            float4 o;
            o.x = acc[i][0] + bb[0]; o.y = acc[i][1] + bb[1];
            o.z = acc[i][2] + bb[2]; o.w = acc[i][3] + bb[3];
            *(float4*)(C + (long)r * BN + 4 * tx) = o;
            if (TN == 8) {
                float4 o2;
                o2.x = acc[i][4] + bb[4]; o2.y = acc[i][5] + bb[5];
                o2.z = acc[i][6] + bb[6]; o2.w = acc[i][7] + bb[7];
                *(float4*)(C + (long)r * BN + 64 + 4 * tx) = o2;
            }
        }
    }

    // fused attention-logit epilogue (BN==64 configs only)
    if (ALH > 0) {
        float as4[4], ad4[4];
#pragma unroll
        for (int j = 0; j < 4; j++) {
            as4[j] = a_src[4 * tx + j];
            ad4[j] = a_dst[4 * tx + j];
        }
#pragma unroll
        for (int i = 0; i < 4; i++) {
            float ps = 0.f, pd = 0.f;
#pragma unroll
            for (int j = 0; j < 4; j++) {
                ps = fmaf(acc[i][j], as4[j], ps);
                pd = fmaf(acc[i][j], ad4[j], pd);
            }
            int r = rowBase + 4 * ty + i;
            if (ALH == 8) {
                ps += __shfl_xor_sync(0xffffffffu, ps, 1);
                pd += __shfl_xor_sync(0xffffffffu, pd, 1);
                if (!(tx & 1) && r < nrows) {
                    al_s[(long)r * 8 + (tx >> 1)] = ps;
                    al_d[(long)r * 8 + (tx >> 1)] = pd;
                }
            } else {
#pragma unroll
                for (int off = 8; off >= 1; off >>= 1) {
                    ps += __shfl_xor_sync(0xffffffffu, ps, off);
                    pd += __shfl_xor_sync(0xffffffffu, pd, off);
                }
                if (tx == 0 && r < nrows) { al_s[r] = ps; al_d[r] = pd; }
            }
        }
    }
}

// ---------------- CSR build ----------------
__global__ void k_zero()
{
    int i = blockIdx.x * blockDim.x + threadIdx.x;
    if (i < NN) g_deg[i] = 0;
}
__global__ void k_hist(const int* __restrict__ ei)
{
    int e = blockIdx.x * blockDim.x + threadIdx.x;
    if (e < NE) atomicAdd(&g_deg[ei[NE + e]], 1);
}
__global__ void k_scan1()
{
    __shared__ int s[256];
    int tid = threadIdx.x;
    int base = blockIdx.x * 1024 + tid * 4;
    int v0 = (base + 0 < NN) ? g_deg[base + 0] : 0;
    int v1 = (base + 1 < NN) ? g_deg[base + 1] : 0;
    int v2 = (base + 2 < NN) ? g_deg[base + 2] : 0;
    int v3 = (base + 3 < NN) ? g_deg[base + 3] : 0;
    v1 += v0; v2 += v1; v3 += v2;
    int tot = v3;
    s[tid] = tot;
    __syncthreads();
    for (int off = 1; off < 256; off <<= 1) {
        int x = (tid >= off) ? s[tid - off] : 0;
        __syncthreads();
        s[tid] += x;
        __syncthreads();
    }
    int excl = s[tid] - tot;
    if (base + 0 < NN) g_scantmp[base + 0] = v0 + excl;
    if (base + 1 < NN) g_scantmp[base + 1] = v1 + excl;
    if (base + 2 < NN) g_scantmp[base + 2] = v2 + excl;
    if (base + 3 < NN) g_scantmp[base + 3] = v3 + excl;
    if (tid == 255) g_bsum[blockIdx.x] = s[255];
}
__global__ void k_scan2()
{
    __shared__ int s[128];
    int tid = threadIdx.x;
    int nb = (NN + 1023) / 1024;
    int v = (tid < nb) ? g_bsum[tid] : 0;
    s[tid] = v;
    __syncthreads();
    for (int off = 1; off < 128; off <<= 1) {
        int x = (tid >= off) ? s[tid - off] : 0;
        __syncthreads();
        s[tid] += x;
        __syncthreads();
    }
    if (tid < nb) g_bsum[tid] = s[tid] - v;  // exclusive
}
__global__ void k_scan3()
{
    int i = blockIdx.x * blockDim.x + threadIdx.x;
    if (i > NN) return;
    int v = (i == 0) ? 0 : (g_scantmp[i - 1] + g_bsum[(i - 1) >> 10]);
    g_rowptr[i] = v;
    if (i < NN) g_cursor[i] = v;
}
__global__ void k_scatter(const int* __restrict__ ei)
{
    int e = blockIdx.x * blockDim.x + threadIdx.x;
    if (e >= NE) return;
    int dst = ei[NE + e];
    int pos = atomicAdd(&g_cursor[dst], 1);
    g_col[pos] = ei[e];
}

// ---------------- GAT layer 1 aggregation (8 heads, direct exp — logits bounded) ----
__global__ void __launch_bounds__(256)
k_gat1(const float* __restrict__ b1)
{
    int node = (blockIdx.x * blockDim.x + threadIdx.x) >> 5;
    int lane = threadIdx.x & 31;
    if (node >= NN) return;
    int hl = lane >> 2;                // head owning features {2*lane, 2*lane+1}
    float ald = g_al_d1[(long)node * 8 + hl];

    // self-loop
    float e0 = g_al_s1[(long)node * 8 + hl] + ald;
    e0 = fmaxf(e0, 0.2f * e0);         // leaky_relu
    float w0 = __expf(e0);
    float d = w0;
    ull acc = mul2(pk2(w0, w0), *(const ull*)(g_xW1 + (long)node * 64 + 2 * lane));

    int beg = g_rowptr[node], end = g_rowptr[node + 1];
    for (int i = beg; i < end; i++) {
        int src = g_col[i];
        float e = g_al_s1[(long)src * 8 + hl] + ald;
        e = fmaxf(e, 0.2f * e);
        float w = __expf(e);
        d += w;
        acc = fma2(pk2(w, w), *(const ull*)(g_xW1 + (long)src * 64 + 2 * lane), acc);
    }
    float ax, ay; upk2(acc, ax, ay);
    float inv = 1.f / d;
    float ox = ax * inv + b1[2 * lane];
    float oy = ay * inv + b1[2 * lane + 1];
    ox = (ox > 0.f) ? ox : expm1f(ox);
    oy = (oy > 0.f) ? oy : expm1f(oy);
    *(float2*)(g_h1 + (long)node * 64 + 2 * lane) = make_float2(ox, oy);
}

// ---------------- GAT layer 2 aggregation (1 head) ----------------
__global__ void __launch_bounds__(256)
k_gat2(const float* __restrict__ b2)
{
    int node = (blockIdx.x * blockDim.x + threadIdx.x) >> 5;
    int lane = threadIdx.x & 31;
    if (node >= NN) return;
    float ald = g_al_d2[node];
    float e0 = g_al_s2[node] + ald;
    e0 = fmaxf(e0, 0.2f * e0);
    float w0 = __expf(e0);
    float d = w0;
    ull acc = mul2(pk2(w0, w0), *(const ull*)(g_xW2 + (long)node * 64 + 2 * lane));

    int beg = g_rowptr[node], end = g_rowptr[node + 1];
    for (int i = beg; i < end; i++) {
        int src = g_col[i];
        float e = g_al_s2[src] + ald;
        e = fmaxf(e, 0.2f * e);
        float w = __expf(e);
        d += w;
        acc = fma2(pk2(w, w), *(const ull*)(g_xW2 + (long)src * 64 + 2 * lane), acc);
    }
    float ax, ay; upk2(acc, ax, ay);
    float inv = 1.f / d;
    float ox = ax * inv + b2[2 * lane];
    float oy = ay * inv + b2[2 * lane + 1];
    ox = (ox > 0.f) ? ox : expm1f(ox);
    oy = (oy > 0.f) ? oy : expm1f(oy);
    *(float2*)(g_h2 + (long)node * 64 + 2 * lane) = make_float2(ox, oy);
}

// ---------------- fold lin_W (+bias) into mlp_W1 halves ----------------
__global__ void k_fold(const float* __restrict__ linW, const float* __restrict__ linb,
                       const float* __restrict__ mW1)
{
    int b = blockIdx.x;           // 129 blocks
    int c = threadIdx.x;          // 128 threads
    if (b < 128) {
        int i = b & 63;
        int off = (b >> 6) ? 64 : 0;
        float s = 0.f;
        for (int j = 0; j < 64; j++)
            s = fmaf(linW[i * 64 + j], mW1[(off + j) * 128 + c], s);
        ((b >> 6) ? g_Wlb : g_Wla)[i * 128 + c] = s;
    } else {
        float s0 = 0.f, s1 = 0.f;
        for (int j = 0; j < 64; j++) {
            s0 = fmaf(linb[j], mW1[j * 128 + c], s0);
            s1 = fmaf(linb[j], mW1[(64 + j) * 128 + c], s1);
        }
        g_bP[c] = s0;
        g_bQ[c] = s1;
    }
}

// ---------------- edge MLP + log_softmax (edge-parallel, f32x2 math) ----------------
__global__ void __launch_bounds__(256, 2)
k_edge(const int* __restrict__ ei, const float* __restrict__ ea,
       const float* __restrict__ mW1, const float* __restrict__ mb1,
       const float* __restrict__ mW2, const float* __restrict__ mb2,
       float* __restrict__ out)
{
    int lane = threadIdx.x & 31;
    int warp = (blockIdx.x * blockDim.x + threadIdx.x) >> 5;
    int nwarps = (gridDim.x * blockDim.x) >> 5;

    ull wc2[16][2];
#pragma unroll
    for (int k = 0; k < 16; k++) {
        ulonglong2 v = *(const ulonglong2*)(mW1 + (long)(128 + k) * 128 + 4 * lane);
        wc2[k][0] = v.x; wc2[k][1] = v.y;
    }
    float w2a[4], w2b[4];
#pragma unroll
    for (int u = 0; u < 4; u++) {
        int j = 4 * lane + u;
        w2a[u] = mW2[j * 2 + 0];
        w2b[u] = mW2[j * 2 + 1];
    }
    ull br2[2];
    {
        float4 b = *(const float4*)(mb1 + 4 * lane);
        br2[0] = pk2(b.x, b.y);
        br2[1] = pk2(b.z, b.w);
    }
    float b20 = mb2[0], b21 = mb2[1];

    for (int e = warp; e < NE; e += nwarps) {
        int src = ei[e];
        int dst = ei[NE + e];
        float eal = (lane < 16) ? ea[(long)e * 16 + lane] : 0.f;
        ulonglong2 P2 = *(const ulonglong2*)(g_P + (long)src * 128 + 4 * lane);
        ulonglong2 Q2 = *(const ulonglong2*)(g_Q + (long)dst * 128 + 4 * lane);
        ull h0 = add2(add2(P2.x, Q2.x), br2[0]);
        ull h1 = add2(add2(P2.y, Q2.y), br2[1]);
#pragma unroll
        for (int k = 0; k < 16; k++) {
            float ek = __shfl_sync(0xffffffffu, eal, k);
            ull ekk = pk2(ek, ek);
            h0 = fma2(ekk, wc2[k][0], h0);
            h1 = fma2(ekk, wc2[k][1], h1);
        }
        float ha, hb, hc, hd;
        upk2(h0, ha, hb);
        upk2(h1, hc, hd);
        ha = fmaxf(ha, 0.f); hb = fmaxf(hb, 0.f);
        hc = fmaxf(hc, 0.f); hd = fmaxf(hd, 0.f);
        float s0 = fmaf(ha, w2a[0], fmaf(hb, w2a[1], fmaf(hc, w2a[2], hd * w2a[3])));
        float s1 = fmaf(ha, w2b[0], fmaf(hb, w2b[1], fmaf(hc, w2b[2], hd * w2b[3])));
#pragma unroll
        for (int off = 16; off >= 1; off >>= 1) {
            s0 += __shfl_xor_sync(0xffffffffu, s0, off);
            s1 += __shfl_xor_sync(0xffffffffu, s1, off);
        }
        if (lane == 0) {
            float o0 = s0 + b20, o1 = s1 + b21;
            float mx = fmaxf(o0, o1), mn = fminf(o0, o1);
            float l = mx + log1pf(expf(mn - mx));
            *(float2*)(out + (long)e * 2) = make_float2(o0 - l, o1 - l);
        }
    }
}

// ---------------- host ----------------
extern "C" void kernel_launch(void* const* d_in, const int* in_sizes, int n_in,
                              void* d_out, int out_size)
{
    (void)in_sizes; (void)n_in; (void)out_size;
    const float* x    = (const float*)d_in[0];
    const int*   ei   = (const int*)d_in[1];
    const float* eatt = (const float*)d_in[2];
    const float* W1   = (const float*)d_in[3];
    const float* as1  = (const float*)d_in[4];
    const float* ad1  = (const float*)d_in[5];
    const float* b1   = (const float*)d_in[6];
    const float* W2   = (const float*)d_in[7];
    const float* as2  = (const float*)d_in[8];
    const float* ad2  = (const float*)d_in[9];
    const float* b2   = (const float*)d_in[10];
    const float* linW = (const float*)d_in[11];
    const float* linb = (const float*)d_in[12];
    const float* mW1  = (const float*)d_in[13];
    const float* mb1  = (const float*)d_in[14];
    const float* mW2  = (const float*)d_in[15];
    const float* mb2  = (const float*)d_in[16];
    float* out = (float*)d_out;

    void *p_xW1, *p_als1, *p_ald1, *p_h1, *p_xW2, *p_als2, *p_ald2, *p_h2;
    void *p_P, *p_Q, *p_Wla, *p_Wlb, *p_bP, *p_bQ;
    cudaGetSymbolAddress(&p_xW1, g_xW1);
    cudaGetSymbolAddress(&p_als1, g_al_s1);
    cudaGetSymbolAddress(&p_ald1, g_al_d1);
    cudaGetSymbolAddress(&p_h1, g_h1);
    cudaGetSymbolAddress(&p_xW2, g_xW2);
    cudaGetSymbolAddress(&p_als2, g_al_s2);
    cudaGetSymbolAddress(&p_ald2, g_al_d2);
    cudaGetSymbolAddress(&p_h2, g_h2);
    cudaGetSymbolAddress(&p_P, g_P);
    cudaGetSymbolAddress(&p_Q, g_Q);
    cudaGetSymbolAddress(&p_Wla, g_Wla);
    cudaGetSymbolAddress(&p_Wlb, g_Wlb);
    cudaGetSymbolAddress(&p_bP, g_bP);
    cudaGetSymbolAddress(&p_bQ, g_bQ);

    const int GEMM_BLOCKS = (NN + 63) / 64;       // 1563
    const int WARP_BLOCKS = (NN + 7) / 8;         // 12500 (warp per node)
    const int EDGE_BLOCKS = (NE + 255) / 256;     // 6250

    // Side stream for the CSR chain (falls back to sequential stream 0 on failure;
    // submission order is sequentially correct in that case).
    cudaStream_t s1 = 0;
    cudaEvent_t eFork = 0, eJoin = 0, eFork2 = 0, eJoin2 = 0;
    bool par = (cudaStreamCreateWithFlags(&s1, cudaStreamNonBlocking) == cudaSuccess);
    if (par) {
        par = (cudaEventCreateWithFlags(&eFork,  cudaEventDisableTiming) == cudaSuccess) &&
              (cudaEventCreateWithFlags(&eJoin,  cudaEventDisableTiming) == cudaSuccess) &&
              (cudaEventCreateWithFlags(&eFork2, cudaEventDisableTiming) == cudaSuccess) &&
              (cudaEventCreateWithFlags(&eJoin2, cudaEventDisableTiming) == cudaSuccess);
        if (!par) s1 = 0;
    }

    if (par) { cudaEventRecord(eFork, 0); cudaStreamWaitEvent(s1, eFork, 0); }

    // CSR chain on side stream (independent of GEMM1)
    k_zero<<<(NN + 255) / 256, 256, 0, s1>>>();
    k_hist<<<EDGE_BLOCKS, 256, 0, s1>>>(ei);
    k_scan1<<<(NN + 1023) / 1024, 256, 0, s1>>>();

    // GAT layer 1 projection + fused attention logits (4th launch = ncu slot)
    k_gemm<128, 64, 4, 8><<<GEMM_BLOCKS, 256>>>(x, W1, 64, nullptr, (float*)p_xW1, NN,
                                                as1, ad1, (float*)p_als1, (float*)p_ald1);

    k_scan2<<<1, 128, 0, s1>>>();
    k_scan3<<<(NN + 1 + 255) / 256, 256, 0, s1>>>();
    k_scatter<<<EDGE_BLOCKS, 256, 0, s1>>>(ei);
    k_fold<<<129, 128, 0, s1>>>(linW, linb, mW1);

    if (par) { cudaEventRecord(eJoin, s1); cudaStreamWaitEvent(0, eJoin, 0); }

    k_gat1<<<WARP_BLOCKS, 256>>>(b1);

    // GAT layer 2
    k_gemm<64, 64, 4, 1><<<GEMM_BLOCKS, 256>>>((const float*)p_h1, W2, 64, nullptr,
                                               (float*)p_xW2, NN,
                                               as2, ad2, (float*)p_als2, (float*)p_ald2);
    k_gat2<<<WARP_BLOCKS, 256>>>(b2);

    // P/Q GEMMs: independent of each other -> run concurrently
    if (par) { cudaEventRecord(eFork2, 0); cudaStreamWaitEvent(s1, eFork2, 0); }
    k_gemm<64, 128, 8, 0><<<GEMM_BLOCKS, 256, 0, s1>>>((const float*)p_h2, (const float*)p_Wlb, 128,
                                                       (const float*)p_bQ, (float*)p_Q, NN,
                                                       nullptr, nullptr, nullptr, nullptr);
    k_gemm<64, 128, 8, 0><<<GEMM_BLOCKS, 256>>>((const float*)p_h2, (const float*)p_Wla, 128,
                                                (const float*)p_bP, (float*)p_P, NN,
                                                nullptr, nullptr, nullptr, nullptr);
    if (par) { cudaEventRecord(eJoin2, s1); cudaStreamWaitEvent(0, eJoin2, 0); }

    // edge MLP + log_softmax (ea and out fully streamed; P/Q random but L2-resident)
    k_edge<<<2368, 256>>>(ei, eatt, mW1, mb1, mW2, mb2, out);
}

// round 8
// speedup vs baseline: 1.9506x; 1.2732x over previous
#include <cuda_runtime.h>
#include <math.h>

#define NN 100000
#define NE 1600000

typedef unsigned long long ull;

// ---------------- f32x2 packed math (sm_100+; ptxas never emits these from C++) ----
__device__ __forceinline__ ull pk2(float lo, float hi) {
    ull r; asm("mov.b64 %0, {%1, %2};" : "=l"(r) : "f"(lo), "f"(hi)); return r;
}
__device__ __forceinline__ void upk2(ull v, float& lo, float& hi) {
    asm("mov.b64 {%0, %1}, %2;" : "=f"(lo), "=f"(hi) : "l"(v));
}
__device__ __forceinline__ ull fma2(ull a, ull b, ull c) {
    ull d; asm("fma.rn.f32x2 %0, %1, %2, %3;" : "=l"(d) : "l"(a), "l"(b), "l"(c)); return d;
}
__device__ __forceinline__ ull add2(ull a, ull b) {
    ull d; asm("add.rn.f32x2 %0, %1, %2;" : "=l"(d) : "l"(a), "l"(b)); return d;
}
__device__ __forceinline__ ull mul2(ull a, ull b) {
    ull d; asm("mul.rn.f32x2 %0, %1, %2;" : "=l"(d) : "l"(a), "l"(b)); return d;
}

// ---------------- scratch (device globals; no allocation allowed) ----------------
__device__ float g_xW1[NN * 64];
__device__ float g_al_s1[NN * 8];
__device__ float g_al_d1[NN * 8];
__device__ float g_h1[NN * 64];
__device__ float g_xW2[NN * 64];
__device__ float g_al_s2[NN];
__device__ float g_al_d2[NN];
__device__ float g_h2[NN * 64];
__device__ float g_P[NN * 128];
__device__ float g_Q[NN * 128];
__device__ float g_Wla[64 * 128];
__device__ float g_Wlb[64 * 128];
__device__ float g_bP[128];
__device__ float g_bQ[128];
__device__ int   g_deg[NN];
__device__ int   g_cursor[NN];
__device__ int   g_scantmp[NN];
__device__ int   g_rowptr[NN + 1];
__device__ int   g_bsum[128];
__device__ int   g_col[NE];

// ---------------- GEMM: C[nrows,BN] = A[nrows,K] @ B[K,BN] (+bias)
// BM=128, microtile 8 rows x TN cols per thread, 256 threads.
// ALH: 0 = plain, 8 = fused 8-head attention logits, 1 = fused 1-head logits
template <int K, int BN, int TN, int ALH>
__global__ void __launch_bounds__(256)
k_gemm(const float* __restrict__ A, const float* __restrict__ B, int ldb,
       const float* __restrict__ bias, float* __restrict__ C, int nrows,
       const float* __restrict__ a_src, const float* __restrict__ a_dst,
       float* __restrict__ al_s, float* __restrict__ al_d)
{
    constexpr int BM = 128, KC = 16, PAD = 132;
    __shared__ __align__(16) float sB[K * BN];
    __shared__ __align__(16) float sA[KC * PAD];
    const int tid = threadIdx.x;
    const int tx = tid & 15, tyr = tid >> 4;     // tx: col group, tyr: row group (8 rows)
    const int rowBase = blockIdx.x * BM;

    for (int i = tid; i < K * BN; i += 256)
        sB[i] = B[(i / BN) * ldb + (i % BN)];

    ull accp[8][TN / 2];
#pragma unroll
    for (int i = 0; i < 8; i++)
#pragma unroll
        for (int j = 0; j < TN / 2; j++) accp[i][j] = pk2(0.f, 0.f);

    const int rL = tid & 127;               // row this thread stages
    const int k4 = (tid >> 7) * 8;          // k-offset (0 or 8)

    for (int kc = 0; kc < K; kc += KC) {
        __syncthreads();
        {
            int gr = rowBase + rL;
            float4 av0 = make_float4(0.f, 0.f, 0.f, 0.f);
            float4 av1 = make_float4(0.f, 0.f, 0.f, 0.f);
            if (gr < nrows) {
                av0 = *(const float4*)(A + (long)gr * K + kc + k4);
                av1 = *(const float4*)(A + (long)gr * K + kc + k4 + 4);
            }
            sA[(k4 + 0) * PAD + rL] = av0.x;
            sA[(k4 + 1) * PAD + rL] = av0.y;
            sA[(k4 + 2) * PAD + rL] = av0.z;
            sA[(k4 + 3) * PAD + rL] = av0.w;
            sA[(k4 + 4) * PAD + rL] = av1.x;
            sA[(k4 + 5) * PAD + rL] = av1.y;
            sA[(k4 + 6) * PAD + rL] = av1.z;
            sA[(k4 + 7) * PAD + rL] = av1.w;
        }
        __syncthreads();
#pragma unroll
        for (int kk = 0; kk < KC; kk++) {
            float4 a0 = *(const float4*)&sA[kk * PAD + 8 * tyr];
            float4 a1 = *(const float4*)&sA[kk * PAD + 8 * tyr + 4];
            ull bv[TN / 2];
            {
                ulonglong2 b2 = *(const ulonglong2*)&sB[(kc + kk) * BN + 4 * tx];
                bv[0] = b2.x; bv[1] = b2.y;
                if (TN == 8) {
                    ulonglong2 b3 = *(const ulonglong2*)&sB[(kc + kk) * BN + 64 + 4 * tx];
                    bv[2] = b3.x; bv[3] = b3.y;
                }
            }
            float av8[8] = {a0.x, a0.y, a0.z, a0.w, a1.x, a1.y, a1.z, a1.w};
#pragma unroll
            for (int i = 0; i < 8; i++) {
                ull ap = pk2(av8[i], av8[i]);
#pragma unroll
                for (int j = 0; j < TN / 2; j++)
                    accp[i][j] = fma2(ap, bv[j], accp[i][j]);
            }
        }
    }

    float acc[8][TN];
#pragma unroll
    for (int i = 0; i < 8; i++)
#pragma unroll
        for (int j = 0; j < TN / 2; j++)
            upk2(accp[i][j], acc[i][2 * j], acc[i][2 * j + 1]);

    float bb[TN];
#pragma unroll
    for (int j = 0; j < TN; j++) {
        int col = (j < 4) ? (4 * tx + j) : (64 + 4 * tx + (j - 4));
        bb[j] = bias ? bias[col] : 0.f;
    }
#pragma unroll
    for (int i = 0; i < 8; i++) {
        int r = rowBase + 8 * tyr + i;
        if (r < nrows) {
            float4 o;
            o.x = acc[i][0] + bb[0]; o.y = acc[i][1] + bb[1];
            o.z = acc[i][2] + bb[2]; o.w = acc[i][3] + bb[3];
            *(float4*)(C + (long)r * BN + 4 * tx) = o;
            if (TN == 8) {
                float4 o2;
                o2.x = acc[i][4] + bb[4]; o2.y = acc[i][5] + bb[5];
                o2.z = acc[i][6] + bb[6]; o2.w = acc[i][7] + bb[7];
                *(float4*)(C + (long)r * BN + 64 + 4 * tx) = o2;
            }
        }
    }

    // fused attention-logit epilogue (BN==64 configs only)
    if (ALH > 0) {
        float as4[4], ad4[4];
#pragma unroll
        for (int j = 0; j < 4; j++) {
            as4[j] = a_src[4 * tx + j];
            ad4[j] = a_dst[4 * tx + j];
        }
#pragma unroll
        for (int i = 0; i < 8; i++) {
            float ps = 0.f, pd = 0.f;
#pragma unroll
            for (int j = 0; j < 4; j++) {
                ps = fmaf(acc[i][j], as4[j], ps);
                pd = fmaf(acc[i][j], ad4[j], pd);
            }
            int r = rowBase + 8 * tyr + i;
            if (ALH == 8) {
                ps += __shfl_xor_sync(0xffffffffu, ps, 1);
                pd += __shfl_xor_sync(0xffffffffu, pd, 1);
                if (!(tx & 1) && r < nrows) {
                    al_s[(long)r * 8 + (tx >> 1)] = ps;
                    al_d[(long)r * 8 + (tx >> 1)] = pd;
                }
            } else {
#pragma unroll
                for (int off = 8; off >= 1; off >>= 1) {
                    ps += __shfl_xor_sync(0xffffffffu, ps, off);
                    pd += __shfl_xor_sync(0xffffffffu, pd, off);
                }
                if (tx == 0 && r < nrows) { al_s[r] = ps; al_d[r] = pd; }
            }
        }
    }
}

// ---------------- CSR build ----------------
__global__ void k_zero()
{
    int i = blockIdx.x * blockDim.x + threadIdx.x;
    if (i < NN) g_deg[i] = 0;
}
__global__ void k_hist(const int* __restrict__ ei)
{
    int e = blockIdx.x * blockDim.x + threadIdx.x;
    if (e < NE) atomicAdd(&g_deg[ei[NE + e]], 1);
}
__global__ void k_scan1()
{
    __shared__ int s[256];
    int tid = threadIdx.x;
    int base = blockIdx.x * 1024 + tid * 4;
    int v0 = (base + 0 < NN) ? g_deg[base + 0] : 0;
    int v1 = (base + 1 < NN) ? g_deg[base + 1] : 0;
    int v2 = (base + 2 < NN) ? g_deg[base + 2] : 0;
    int v3 = (base + 3 < NN) ? g_deg[base + 3] : 0;
    v1 += v0; v2 += v1; v3 += v2;
    int tot = v3;
    s[tid] = tot;
    __syncthreads();
    for (int off = 1; off < 256; off <<= 1) {
        int x = (tid >= off) ? s[tid - off] : 0;
        __syncthreads();
        s[tid] += x;
        __syncthreads();
    }
    int excl = s[tid] - tot;
    if (base + 0 < NN) g_scantmp[base + 0] = v0 + excl;
    if (base + 1 < NN) g_scantmp[base + 1] = v1 + excl;
    if (base + 2 < NN) g_scantmp[base + 2] = v2 + excl;
    if (base + 3 < NN) g_scantmp[base + 3] = v3 + excl;
    if (tid == 255) g_bsum[blockIdx.x] = s[255];
}
__global__ void k_scan2()
{
    __shared__ int s[128];
    int tid = threadIdx.x;
    int nb = (NN + 1023) / 1024;
    int v = (tid < nb) ? g_bsum[tid] : 0;
    s[tid] = v;
    __syncthreads();
    for (int off = 1; off < 128; off <<= 1) {
        int x = (tid >= off) ? s[tid - off] : 0;
        __syncthreads();
        s[tid] += x;
        __syncthreads();
    }
    if (tid < nb) g_bsum[tid] = s[tid] - v;  // exclusive
}
__global__ void k_scan3()
{
    int i = blockIdx.x * blockDim.x + threadIdx.x;
    if (i > NN) return;
    int v = (i == 0) ? 0 : (g_scantmp[i - 1] + g_bsum[(i - 1) >> 10]);
    g_rowptr[i] = v;
    if (i < NN) g_cursor[i] = v;
}
__global__ void k_scatter(const int* __restrict__ ei)
{
    int e = blockIdx.x * blockDim.x + threadIdx.x;
    if (e >= NE) return;
    int dst = ei[NE + e];
    int pos = atomicAdd(&g_cursor[dst], 1);
    g_col[pos] = ei[e];
}

// ---------------- GAT layer 1 aggregation (8 heads, depth-1 SW pipeline) ----------
__global__ void __launch_bounds__(256)
k_gat1(const float* __restrict__ b1)
{
    int node = (blockIdx.x * blockDim.x + threadIdx.x) >> 5;
    int lane = threadIdx.x & 31;
    if (node >= NN) return;
    int hl = lane >> 2;                // head owning features {2*lane, 2*lane+1}
    float ald = g_al_d1[(long)node * 8 + hl];

    // self-loop
    float e0 = g_al_s1[(long)node * 8 + hl] + ald;
    e0 = fmaxf(e0, 0.2f * e0);
    float w0 = __expf(e0);
    float d = w0;
    ull acc = mul2(pk2(w0, w0), *(const ull*)(g_xW1 + (long)node * 64 + 2 * lane));

    int beg = g_rowptr[node], end = g_rowptr[node + 1];
    float aC = 0.f; ull xC = 0;
    if (beg < end) {
        int s0 = g_col[beg];
        aC = g_al_s1[(long)s0 * 8 + hl];
        xC = *(const ull*)(g_xW1 + (long)s0 * 64 + 2 * lane);
    }
    for (int i = beg; i < end; i++) {
        float aN = 0.f; ull xN = 0;
        if (i + 1 < end) {
            int sN = g_col[i + 1];
            aN = g_al_s1[(long)sN * 8 + hl];
            xN = *(const ull*)(g_xW1 + (long)sN * 64 + 2 * lane);
        }
        float e = aC + ald;
        e = fmaxf(e, 0.2f * e);
        float w = __expf(e);
        d += w;
        acc = fma2(pk2(w, w), xC, acc);
        aC = aN; xC = xN;
    }
    float ax, ay; upk2(acc, ax, ay);
    float inv = 1.f / d;
    float ox = ax * inv + b1[2 * lane];
    float oy = ay * inv + b1[2 * lane + 1];
    ox = (ox > 0.f) ? ox : expm1f(ox);
    oy = (oy > 0.f) ? oy : expm1f(oy);
    *(float2*)(g_h1 + (long)node * 64 + 2 * lane) = make_float2(ox, oy);
}

// ---------------- GAT layer 2 aggregation (1 head, depth-1 SW pipeline) ----------
__global__ void __launch_bounds__(256)
k_gat2(const float* __restrict__ b2)
{
    int node = (blockIdx.x * blockDim.x + threadIdx.x) >> 5;
    int lane = threadIdx.x & 31;
    if (node >= NN) return;
    float ald = g_al_d2[node];
    float e0 = g_al_s2[node] + ald;
    e0 = fmaxf(e0, 0.2f * e0);
    float w0 = __expf(e0);
    float d = w0;
    ull acc = mul2(pk2(w0, w0), *(const ull*)(g_xW2 + (long)node * 64 + 2 * lane));

    int beg = g_rowptr[node], end = g_rowptr[node + 1];
    float aC = 0.f; ull xC = 0;
    if (beg < end) {
        int s0 = g_col[beg];
        aC = g_al_s2[s0];
        xC = *(const ull*)(g_xW2 + (long)s0 * 64 + 2 * lane);
    }
    for (int i = beg; i < end; i++) {
        float aN = 0.f; ull xN = 0;
        if (i + 1 < end) {
            int sN = g_col[i + 1];
            aN = g_al_s2[sN];
            xN = *(const ull*)(g_xW2 + (long)sN * 64 + 2 * lane);
        }
        float e = aC + ald;
        e = fmaxf(e, 0.2f * e);
        float w = __expf(e);
        d += w;
        acc = fma2(pk2(w, w), xC, acc);
        aC = aN; xC = xN;
    }
    float ax, ay; upk2(acc, ax, ay);
    float inv = 1.f / d;
    float ox = ax * inv + b2[2 * lane];
    float oy = ay * inv + b2[2 * lane + 1];
    ox = (ox > 0.f) ? ox : expm1f(ox);
    oy = (oy > 0.f) ? oy : expm1f(oy);
    *(float2*)(g_h2 + (long)node * 64 + 2 * lane) = make_float2(ox, oy);
}

// ---------------- fold lin_W (+bias) into mlp_W1 halves ----------------
__global__ void k_fold(const float* __restrict__ linW, const float* __restrict__ linb,
                       const float* __restrict__ mW1)
{
    int b = blockIdx.x;           // 129 blocks
    int c = threadIdx.x;          // 128 threads
    if (b < 128) {
        int i = b & 63;
        int off = (b >> 6) ? 64 : 0;
        float s = 0.f;
        for (int j = 0; j < 64; j++)
            s = fmaf(linW[i * 64 + j], mW1[(off + j) * 128 + c], s);
        ((b >> 6) ? g_Wlb : g_Wla)[i * 128 + c] = s;
    } else {
        float s0 = 0.f, s1 = 0.f;
        for (int j = 0; j < 64; j++) {
            s0 = fmaf(linb[j], mW1[j * 128 + c], s0);
            s1 = fmaf(linb[j], mW1[(64 + j) * 128 + c], s1);
        }
        g_bP[c] = s0;
        g_bQ[c] = s1;
    }
}

// ---------------- edge MLP + log_softmax (edge-parallel, 2-edge interleave) -------
__global__ void __launch_bounds__(256, 2)
k_edge(const int* __restrict__ ei, const float* __restrict__ ea,
       const float* __restrict__ mW1, const float* __restrict__ mb1,
       const float* __restrict__ mW2, const float* __restrict__ mb2,
       float* __restrict__ out)
{
    int lane = threadIdx.x & 31;
    int warp = (blockIdx.x * blockDim.x + threadIdx.x) >> 5;
    int nwarps = (gridDim.x * blockDim.x) >> 5;

    ull wc2[16][2];
#pragma unroll
    for (int k = 0; k < 16; k++) {
        ulonglong2 v = *(const ulonglong2*)(mW1 + (long)(128 + k) * 128 + 4 * lane);
        wc2[k][0] = v.x; wc2[k][1] = v.y;
    }
    float w2a[4], w2b[4];
#pragma unroll
    for (int u = 0; u < 4; u++) {
        int j = 4 * lane + u;
        w2a[u] = mW2[j * 2 + 0];
        w2b[u] = mW2[j * 2 + 1];
    }
    ull br2[2];
    {
        float4 b = *(const float4*)(mb1 + 4 * lane);
        br2[0] = pk2(b.x, b.y);
        br2[1] = pk2(b.z, b.w);
    }
    float b20 = mb2[0], b21 = mb2[1];

    for (int e = warp; e < NE; e += 2 * nwarps) {
        int e2 = e + nwarps;
        bool has2 = (e2 < NE);
        int eB = has2 ? e2 : e;

        int srcA = ei[e],  dstA = ei[NE + e];
        int srcB = ei[eB], dstB = ei[NE + eB];
        float ealA = (lane < 16) ? ea[(long)e * 16 + lane] : 0.f;
        float ealB = (lane < 16) ? ea[(long)eB * 16 + lane] : 0.f;
        ulonglong2 PA = *(const ulonglong2*)(g_P + (long)srcA * 128 + 4 * lane);
        ulonglong2 QA = *(const ulonglong2*)(g_Q + (long)dstA * 128 + 4 * lane);
        ulonglong2 PB = *(const ulonglong2*)(g_P + (long)srcB * 128 + 4 * lane);
        ulonglong2 QB = *(const ulonglong2*)(g_Q + (long)dstB * 128 + 4 * lane);

        ull hA0 = add2(add2(PA.x, QA.x), br2[0]);
        ull hA1 = add2(add2(PA.y, QA.y), br2[1]);
        ull hB0 = add2(add2(PB.x, QB.x), br2[0]);
        ull hB1 = add2(add2(PB.y, QB.y), br2[1]);
#pragma unroll
        for (int k = 0; k < 16; k++) {
            float ekA = __shfl_sync(0xffffffffu, ealA, k);
            float ekB = __shfl_sync(0xffffffffu, ealB, k);
            ull eA = pk2(ekA, ekA);
            ull eB2 = pk2(ekB, ekB);
            hA0 = fma2(eA, wc2[k][0], hA0);
            hA1 = fma2(eA, wc2[k][1], hA1);
            hB0 = fma2(eB2, wc2[k][0], hB0);
            hB1 = fma2(eB2, wc2[k][1], hB1);
        }
        float a0, a1, a2, a3, c0, c1, c2, c3;
        upk2(hA0, a0, a1); upk2(hA1, a2, a3);
        upk2(hB0, c0, c1); upk2(hB1, c2, c3);
        a0 = fmaxf(a0, 0.f); a1 = fmaxf(a1, 0.f); a2 = fmaxf(a2, 0.f); a3 = fmaxf(a3, 0.f);
        c0 = fmaxf(c0, 0.f); c1 = fmaxf(c1, 0.f); c2 = fmaxf(c2, 0.f); c3 = fmaxf(c3, 0.f);
        float sA0 = fmaf(a0, w2a[0], fmaf(a1, w2a[1], fmaf(a2, w2a[2], a3 * w2a[3])));
        float sA1 = fmaf(a0, w2b[0], fmaf(a1, w2b[1], fmaf(a2, w2b[2], a3 * w2b[3])));
        float sB0 = fmaf(c0, w2a[0], fmaf(c1, w2a[1], fmaf(c2, w2a[2], c3 * w2a[3])));
        float sB1 = fmaf(c0, w2b[0], fmaf(c1, w2b[1], fmaf(c2, w2b[2], c3 * w2b[3])));
#pragma unroll
        for (int off = 16; off >= 1; off >>= 1) {
            sA0 += __shfl_xor_sync(0xffffffffu, sA0, off);
            sA1 += __shfl_xor_sync(0xffffffffu, sA1, off);
            sB0 += __shfl_xor_sync(0xffffffffu, sB0, off);
            sB1 += __shfl_xor_sync(0xffffffffu, sB1, off);
        }
        if (lane == 0) {
            float o0 = sA0 + b20, o1 = sA1 + b21;
            float mx = fmaxf(o0, o1), mn = fminf(o0, o1);
            float l = mx + log1pf(expf(mn - mx));
            *(float2*)(out + (long)e * 2) = make_float2(o0 - l, o1 - l);
            if (has2) {
                float p0 = sB0 + b20, p1 = sB1 + b21;
                float mx2 = fmaxf(p0, p1), mn2 = fminf(p0, p1);
                float l2 = mx2 + log1pf(expf(mn2 - mx2));
                *(float2*)(out + (long)e2 * 2) = make_float2(p0 - l2, p1 - l2);
            }
        }
    }
}

// ---------------- host ----------------
extern "C" void kernel_launch(void* const* d_in, const int* in_sizes, int n_in,
                              void* d_out, int out_size)
{
    (void)in_sizes; (void)n_in; (void)out_size;
    const float* x    = (const float*)d_in[0];
    const int*   ei   = (const int*)d_in[1];
    const float* eatt = (const float*)d_in[2];
    const float* W1   = (const float*)d_in[3];
    const float* as1  = (const float*)d_in[4];
    const float* ad1  = (const float*)d_in[5];
    const float* b1   = (const float*)d_in[6];
    const float* W2   = (const float*)d_in[7];
    const float* as2  = (const float*)d_in[8];
    const float* ad2  = (const float*)d_in[9];
    const float* b2   = (const float*)d_in[10];
    const float* linW = (const float*)d_in[11];
    const float* linb = (const float*)d_in[12];
    const float* mW1  = (const float*)d_in[13];
    const float* mb1  = (const float*)d_in[14];
    const float* mW2  = (const float*)d_in[15];
    const float* mb2  = (const float*)d_in[16];
    float* out = (float*)d_out;

    void *p_xW1, *p_als1, *p_ald1, *p_h1, *p_xW2, *p_als2, *p_ald2, *p_h2;
    void *p_P, *p_Q, *p_Wla, *p_Wlb, *p_bP, *p_bQ;
    cudaGetSymbolAddress(&p_xW1, g_xW1);
    cudaGetSymbolAddress(&p_als1, g_al_s1);
    cudaGetSymbolAddress(&p_ald1, g_al_d1);
    cudaGetSymbolAddress(&p_h1, g_h1);
    cudaGetSymbolAddress(&p_xW2, g_xW2);
    cudaGetSymbolAddress(&p_als2, g_al_s2);
    cudaGetSymbolAddress(&p_ald2, g_al_d2);
    cudaGetSymbolAddress(&p_h2, g_h2);
    cudaGetSymbolAddress(&p_P, g_P);
    cudaGetSymbolAddress(&p_Q, g_Q);
    cudaGetSymbolAddress(&p_Wla, g_Wla);
    cudaGetSymbolAddress(&p_Wlb, g_Wlb);
    cudaGetSymbolAddress(&p_bP, g_bP);
    cudaGetSymbolAddress(&p_bQ, g_bQ);

    const int G128 = (NN + 127) / 128;            // 782 (BM=128 GEMM)
    const int WARP_BLOCKS = (NN + 7) / 8;         // 12500 (warp per node)
    const int EDGE_BLOCKS = (NE + 255) / 256;     // 6250

    // Side stream for the CSR chain (falls back to sequential stream 0 on failure).
    cudaStream_t s1 = 0;
    cudaEvent_t eFork = 0, eJoin = 0, eFork2 = 0, eJoin2 = 0;
    bool par = (cudaStreamCreateWithFlags(&s1, cudaStreamNonBlocking) == cudaSuccess);
    if (par) {
        par = (cudaEventCreateWithFlags(&eFork,  cudaEventDisableTiming) == cudaSuccess) &&
              (cudaEventCreateWithFlags(&eJoin,  cudaEventDisableTiming) == cudaSuccess) &&
              (cudaEventCreateWithFlags(&eFork2, cudaEventDisableTiming) == cudaSuccess) &&
              (cudaEventCreateWithFlags(&eJoin2, cudaEventDisableTiming) == cudaSuccess);
        if (!par) s1 = 0;
    }

    if (par) { cudaEventRecord(eFork, 0); cudaStreamWaitEvent(s1, eFork, 0); }

    // CSR chain on side stream (independent of GEMM1)
    k_zero<<<(NN + 255) / 256, 256, 0, s1>>>();
    k_hist<<<EDGE_BLOCKS, 256, 0, s1>>>(ei);
    k_scan1<<<(NN + 1023) / 1024, 256, 0, s1>>>();

    // GAT layer 1 projection + fused attention logits (4th launch = ncu slot)
    k_gemm<128, 64, 4, 8><<<G128, 256>>>(x, W1, 64, nullptr, (float*)p_xW1, NN,
                                         as1, ad1, (float*)p_als1, (float*)p_ald1);

    k_scan2<<<1, 128, 0, s1>>>();
    k_scan3<<<(NN + 1 + 255) / 256, 256, 0, s1>>>();
    k_scatter<<<EDGE_BLOCKS, 256, 0, s1>>>(ei);
    k_fold<<<129, 128, 0, s1>>>(linW, linb, mW1);

    if (par) { cudaEventRecord(eJoin, s1); cudaStreamWaitEvent(0, eJoin, 0); }

    k_gat1<<<WARP_BLOCKS, 256>>>(b1);

    // GAT layer 2
    k_gemm<64, 64, 4, 1><<<G128, 256>>>((const float*)p_h1, W2, 64, nullptr,
                                        (float*)p_xW2, NN,
                                        as2, ad2, (float*)p_als2, (float*)p_ald2);
    k_gat2<<<WARP_BLOCKS, 256>>>(b2);

    // P/Q GEMMs: independent of each other -> run concurrently
    if (par) { cudaEventRecord(eFork2, 0); cudaStreamWaitEvent(s1, eFork2, 0); }
    k_gemm<64, 128, 8, 0><<<G128, 256, 0, s1>>>((const float*)p_h2, (const float*)p_Wlb, 128,
                                                (const float*)p_bQ, (float*)p_Q, NN,
                                                nullptr, nullptr, nullptr, nullptr);
    k_gemm<64, 128, 8, 0><<<G128, 256>>>((const float*)p_h2, (const float*)p_Wla, 128,
                                         (const float*)p_bP, (float*)p_P, NN,
                                         nullptr, nullptr, nullptr, nullptr);
    if (par) { cudaEventRecord(eJoin2, s1); cudaStreamWaitEvent(0, eJoin2, 0); }

    // edge MLP + log_softmax (ea and out fully streamed; P/Q random but L2-resident)
    k_edge<<<2368, 256>>>(ei, eatt, mW1, mb1, mW2, mb2, out);
}

// round 9
// speedup vs baseline: 1.9618x; 1.0057x over previous
#include <cuda_runtime.h>
#include <math.h>

#define NN 100000
#define NE 1600000

typedef unsigned long long ull;

// ---------------- f32x2 packed math (sm_100+; ptxas never emits these from C++) ----
__device__ __forceinline__ ull pk2(float lo, float hi) {
    ull r; asm("mov.b64 %0, {%1, %2};" : "=l"(r) : "f"(lo), "f"(hi)); return r;
}
__device__ __forceinline__ void upk2(ull v, float& lo, float& hi) {
    asm("mov.b64 {%0, %1}, %2;" : "=f"(lo), "=f"(hi) : "l"(v));
}
__device__ __forceinline__ ull fma2(ull a, ull b, ull c) {
    ull d; asm("fma.rn.f32x2 %0, %1, %2, %3;" : "=l"(d) : "l"(a), "l"(b), "l"(c)); return d;
}
__device__ __forceinline__ ull add2(ull a, ull b) {
    ull d; asm("add.rn.f32x2 %0, %1, %2;" : "=l"(d) : "l"(a), "l"(b)); return d;
}
__device__ __forceinline__ ull mul2(ull a, ull b) {
    ull d; asm("mul.rn.f32x2 %0, %1, %2;" : "=l"(d) : "l"(a), "l"(b)); return d;
}

// ---------------- scratch (device globals; no allocation allowed) ----------------
__device__ float g_xW1[NN * 64];
__device__ float g_al_s1[NN * 8];
__device__ float g_al_d1[NN * 8];
__device__ float g_h1[NN * 64];
__device__ float g_xW2[NN * 64];
__device__ float g_al_s2[NN];
__device__ float g_al_d2[NN];
__device__ float g_h2[NN * 64];
__device__ float g_P[NN * 128];
__device__ float g_Q[NN * 128];
__device__ float g_Wla[64 * 128];
__device__ float g_Wlb[64 * 128];
__device__ float g_bP[128];
__device__ float g_bQ[128];
__device__ int   g_deg[NN];
__device__ int   g_cursor[NN];
__device__ int   g_scantmp[NN];
__device__ int   g_rowptr[NN + 1];
__device__ int   g_bsum[128];
__device__ int   g_col[NE];

// ---------------- GEMM: C[nrows,BN] = A[nrows,K] @ B[K,BN] (+bias)
// BM=128, microtile 8 rows x TN cols, 256 threads, A-chunk register prefetch.
// ALH: 0 = plain, 8 = fused 8-head attention logits, 1 = fused 1-head logits
template <int K, int BN, int TN, int ALH>
__global__ void __launch_bounds__(256, TN == 8 ? 2 : 3)
k_gemm(const float* __restrict__ A, const float* __restrict__ B, int ldb,
       const float* __restrict__ bias, float* __restrict__ C, int nrows,
       const float* __restrict__ a_src, const float* __restrict__ a_dst,
       float* __restrict__ al_s, float* __restrict__ al_d)
{
    constexpr int BM = 128, KC = 16, PAD = 132;
    __shared__ __align__(16) float sB[K * BN];
    __shared__ __align__(16) float sA[KC * PAD];
    const int tid = threadIdx.x;
    const int tx = tid & 15, tyr = tid >> 4;     // tx: col group, tyr: row group (8 rows)
    const int rowBase = blockIdx.x * BM;

    for (int i = tid; i < K * BN; i += 256)
        sB[i] = B[(i / BN) * ldb + (i % BN)];

    ull accp[8][TN / 2];
#pragma unroll
    for (int i = 0; i < 8; i++)
#pragma unroll
        for (int j = 0; j < TN / 2; j++) accp[i][j] = pk2(0.f, 0.f);

    const int rL = tid & 127;               // row this thread stages
    const int k4 = (tid >> 7) * 8;          // k-offset (0 or 8)
    const int gr = rowBase + rL;
    const bool rowOk = (gr < nrows);

    float4 pa0 = make_float4(0.f, 0.f, 0.f, 0.f);
    float4 pa1 = make_float4(0.f, 0.f, 0.f, 0.f);
    if (rowOk) {
        pa0 = *(const float4*)(A + (long)gr * K + k4);
        pa1 = *(const float4*)(A + (long)gr * K + k4 + 4);
    }
    sA[(k4 + 0) * PAD + rL] = pa0.x;
    sA[(k4 + 1) * PAD + rL] = pa0.y;
    sA[(k4 + 2) * PAD + rL] = pa0.z;
    sA[(k4 + 3) * PAD + rL] = pa0.w;
    sA[(k4 + 4) * PAD + rL] = pa1.x;
    sA[(k4 + 5) * PAD + rL] = pa1.y;
    sA[(k4 + 6) * PAD + rL] = pa1.z;
    sA[(k4 + 7) * PAD + rL] = pa1.w;
    __syncthreads();

    for (int kc = 0; kc < K; kc += KC) {
        const bool more = (kc + KC < K);
        if (more && rowOk) {
            pa0 = *(const float4*)(A + (long)gr * K + kc + KC + k4);
            pa1 = *(const float4*)(A + (long)gr * K + kc + KC + k4 + 4);
        }
#pragma unroll
        for (int kk = 0; kk < KC; kk++) {
            float4 a0 = *(const float4*)&sA[kk * PAD + 8 * tyr];
            float4 a1 = *(const float4*)&sA[kk * PAD + 8 * tyr + 4];
            ull bv[TN / 2];
            {
                ulonglong2 b2 = *(const ulonglong2*)&sB[(kc + kk) * BN + 4 * tx];
                bv[0] = b2.x; bv[1] = b2.y;
                if (TN == 8) {
                    ulonglong2 b3 = *(const ulonglong2*)&sB[(kc + kk) * BN + 64 + 4 * tx];
                    bv[2] = b3.x; bv[3] = b3.y;
                }
            }
            float av8[8] = {a0.x, a0.y, a0.z, a0.w, a1.x, a1.y, a1.z, a1.w};
#pragma unroll
            for (int i = 0; i < 8; i++) {
                ull ap = pk2(av8[i], av8[i]);
#pragma unroll
                for (int j = 0; j < TN / 2; j++)
                    accp[i][j] = fma2(ap, bv[j], accp[i][j]);
            }
        }
        if (more) {
            __syncthreads();
            sA[(k4 + 0) * PAD + rL] = pa0.x;
            sA[(k4 + 1) * PAD + rL] = pa0.y;
            sA[(k4 + 2) * PAD + rL] = pa0.z;
            sA[(k4 + 3) * PAD + rL] = pa0.w;
            sA[(k4 + 4) * PAD + rL] = pa1.x;
            sA[(k4 + 5) * PAD + rL] = pa1.y;
            sA[(k4 + 6) * PAD + rL] = pa1.z;
            sA[(k4 + 7) * PAD + rL] = pa1.w;
            __syncthreads();
        }
    }

    float acc[8][TN];
#pragma unroll
    for (int i = 0; i < 8; i++)
#pragma unroll
        for (int j = 0; j < TN / 2; j++)
            upk2(accp[i][j], acc[i][2 * j], acc[i][2 * j + 1]);

    float bb[TN];
#pragma unroll
    for (int j = 0; j < TN; j++) {
        int col = (j < 4) ? (4 * tx + j) : (64 + 4 * tx + (j - 4));
        bb[j] = bias ? bias[col] : 0.f;
    }
#pragma unroll
    for (int i = 0; i < 8; i++) {
        int r = rowBase + 8 * tyr + i;
        if (r < nrows) {
            float4 o;
            o.x = acc[i][0] + bb[0]; o.y = acc[i][1] + bb[1];
            o.z = acc[i][2] + bb[2]; o.w = acc[i][3] + bb[3];
            *(float4*)(C + (long)r * BN + 4 * tx) = o;
            if (TN == 8) {
                float4 o2;
                o2.x = acc[i][4] + bb[4]; o2.y = acc[i][5] + bb[5];
                o2.z = acc[i][6] + bb[6]; o2.w = acc[i][7] + bb[7];
                *(float4*)(C + (long)r * BN + 64 + 4 * tx) = o2;
            }
        }
    }

    // fused attention-logit epilogue (BN==64 configs only)
    if (ALH > 0) {
        float as4[4], ad4[4];
#pragma unroll
        for (int j = 0; j < 4; j++) {
            as4[j] = a_src[4 * tx + j];
            ad4[j] = a_dst[4 * tx + j];
        }
#pragma unroll
        for (int i = 0; i < 8; i++) {
            float ps = 0.f, pd = 0.f;
#pragma unroll
            for (int j = 0; j < 4; j++) {
                ps = fmaf(acc[i][j], as4[j], ps);
                pd = fmaf(acc[i][j], ad4[j], pd);
            }
            int r = rowBase + 8 * tyr + i;
            if (ALH == 8) {
                ps += __shfl_xor_sync(0xffffffffu, ps, 1);
                pd += __shfl_xor_sync(0xffffffffu, pd, 1);
                if (!(tx & 1) && r < nrows) {
                    al_s[(long)r * 8 + (tx >> 1)] = ps;
                    al_d[(long)r * 8 + (tx >> 1)] = pd;
                }
            } else {
#pragma unroll
                for (int off = 8; off >= 1; off >>= 1) {
                    ps += __shfl_xor_sync(0xffffffffu, ps, off);
                    pd += __shfl_xor_sync(0xffffffffu, pd, off);
                }
                if (tx == 0 && r < nrows) { al_s[r] = ps; al_d[r] = pd; }
            }
        }
    }
}

// ---------------- CSR build ----------------
__global__ void k_zero()
{
    int i = blockIdx.x * blockDim.x + threadIdx.x;
    if (i < NN) g_deg[i] = 0;
}
__global__ void k_hist(const int* __restrict__ ei)
{
    int e = blockIdx.x * blockDim.x + threadIdx.x;
    if (e < NE) atomicAdd(&g_deg[ei[NE + e]], 1);
}
__global__ void k_scan1()
{
    __shared__ int s[256];
    int tid = threadIdx.x;
    int base = blockIdx.x * 1024 + tid * 4;
    int v0 = (base + 0 < NN) ? g_deg[base + 0] : 0;
    int v1 = (base + 1 < NN) ? g_deg[base + 1] : 0;
    int v2 = (base + 2 < NN) ? g_deg[base + 2] : 0;
    int v3 = (base + 3 < NN) ? g_deg[base + 3] : 0;
    v1 += v0; v2 += v1; v3 += v2;
    int tot = v3;
    s[tid] = tot;
    __syncthreads();
    for (int off = 1; off < 256; off <<= 1) {
        int x = (tid >= off) ? s[tid - off] : 0;
        __syncthreads();
        s[tid] += x;
        __syncthreads();
    }
    int excl = s[tid] - tot;
    if (base + 0 < NN) g_scantmp[base + 0] = v0 + excl;
    if (base + 1 < NN) g_scantmp[base + 1] = v1 + excl;
    if (base + 2 < NN) g_scantmp[base + 2] = v2 + excl;
    if (base + 3 < NN) g_scantmp[base + 3] = v3 + excl;
    if (tid == 255) g_bsum[blockIdx.x] = s[255];
}
__global__ void k_scan2()
{
    __shared__ int s[128];
    int tid = threadIdx.x;
    int nb = (NN + 1023) / 1024;
    int v = (tid < nb) ? g_bsum[tid] : 0;
    s[tid] = v;
    __syncthreads();
    for (int off = 1; off < 128; off <<= 1) {
        int x = (tid >= off) ? s[tid - off] : 0;
        __syncthreads();
        s[tid] += x;
        __syncthreads();
    }
    if (tid < nb) g_bsum[tid] = s[tid] - v;  // exclusive
}
__global__ void k_scan3()
{
    int i = blockIdx.x * blockDim.x + threadIdx.x;
    if (i > NN) return;
    int v = (i == 0) ? 0 : (g_scantmp[i - 1] + g_bsum[(i - 1) >> 10]);
    g_rowptr[i] = v;
    if (i < NN) g_cursor[i] = v;
}
__global__ void k_scatter(const int* __restrict__ ei)
{
    int e = blockIdx.x * blockDim.x + threadIdx.x;
    if (e >= NE) return;
    int dst = ei[NE + e];
    int pos = atomicAdd(&g_cursor[dst], 1);
    g_col[pos] = ei[e];
}

// ---------------- GAT layer 1 aggregation (8 heads, depth-2 SW pipeline) ----------
__global__ void __launch_bounds__(256)
k_gat1(const float* __restrict__ b1)
{
    int node = (blockIdx.x * blockDim.x + threadIdx.x) >> 5;
    int lane = threadIdx.x & 31;
    if (node >= NN) return;
    int hl = lane >> 2;                // head owning features {2*lane, 2*lane+1}
    float ald = g_al_d1[(long)node * 8 + hl];

    // self-loop
    float e0 = g_al_s1[(long)node * 8 + hl] + ald;
    e0 = fmaxf(e0, 0.2f * e0);
    float w0 = __expf(e0);
    float d = w0;
    ull acc = mul2(pk2(w0, w0), *(const ull*)(g_xW1 + (long)node * 64 + 2 * lane));

    int beg = g_rowptr[node];
    int n = g_rowptr[node + 1] - beg;
    float a0 = 0.f, a1 = 0.f; ull x0 = 0, x1 = 0;
    if (n > 0) {
        int s = g_col[beg];
        a0 = g_al_s1[(long)s * 8 + hl];
        x0 = *(const ull*)(g_xW1 + (long)s * 64 + 2 * lane);
    }
    if (n > 1) {
        int s = g_col[beg + 1];
        a1 = g_al_s1[(long)s * 8 + hl];
        x1 = *(const ull*)(g_xW1 + (long)s * 64 + 2 * lane);
    }
    int i = 0;
    for (; i + 1 < n; i += 2) {
        float aC0 = a0; ull xC0 = x0;
        if (i + 2 < n) {
            int s = g_col[beg + i + 2];
            a0 = g_al_s1[(long)s * 8 + hl];
            x0 = *(const ull*)(g_xW1 + (long)s * 64 + 2 * lane);
        }
        float aC1 = a1; ull xC1 = x1;
        if (i + 3 < n) {
            int s = g_col[beg + i + 3];
            a1 = g_al_s1[(long)s * 8 + hl];
            x1 = *(const ull*)(g_xW1 + (long)s * 64 + 2 * lane);
        }
        float e = aC0 + ald;
        e = fmaxf(e, 0.2f * e);
        float w = __expf(e);
        d += w;
        acc = fma2(pk2(w, w), xC0, acc);
        e = aC1 + ald;
        e = fmaxf(e, 0.2f * e);
        w = __expf(e);
        d += w;
        acc = fma2(pk2(w, w), xC1, acc);
    }
    if (i < n) {
        float e = a0 + ald;
        e = fmaxf(e, 0.2f * e);
        float w = __expf(e);
        d += w;
        acc = fma2(pk2(w, w), x0, acc);
    }
    float ax, ay; upk2(acc, ax, ay);
    float inv = 1.f / d;
    float ox = ax * inv + b1[2 * lane];
    float oy = ay * inv + b1[2 * lane + 1];
    ox = (ox > 0.f) ? ox : expm1f(ox);
    oy = (oy > 0.f) ? oy : expm1f(oy);
    *(float2*)(g_h1 + (long)node * 64 + 2 * lane) = make_float2(ox, oy);
}

// ---------------- GAT layer 2 aggregation (1 head, depth-2 SW pipeline) ----------
__global__ void __launch_bounds__(256)
k_gat2(const float* __restrict__ b2)
{
    int node = (blockIdx.x * blockDim.x + threadIdx.x) >> 5;
    int lane = threadIdx.x & 31;
    if (node >= NN) return;
    float ald = g_al_d2[node];
    float e0 = g_al_s2[node] + ald;
    e0 = fmaxf(e0, 0.2f * e0);
    float w0 = __expf(e0);
    float d = w0;
    ull acc = mul2(pk2(w0, w0), *(const ull*)(g_xW2 + (long)node * 64 + 2 * lane));

    int beg = g_rowptr[node];
    int n = g_rowptr[node + 1] - beg;
    float a0 = 0.f, a1 = 0.f; ull x0 = 0, x1 = 0;
    if (n > 0) {
        int s = g_col[beg];
        a0 = g_al_s2[s];
        x0 = *(const ull*)(g_xW2 + (long)s * 64 + 2 * lane);
    }
    if (n > 1) {
        int s = g_col[beg + 1];
        a1 = g_al_s2[s];
        x1 = *(const ull*)(g_xW2 + (long)s * 64 + 2 * lane);
    }
    int i = 0;
    for (; i + 1 < n; i += 2) {
        float aC0 = a0; ull xC0 = x0;
        if (i + 2 < n) {
            int s = g_col[beg + i + 2];
            a0 = g_al_s2[s];
            x0 = *(const ull*)(g_xW2 + (long)s * 64 + 2 * lane);
        }
        float aC1 = a1; ull xC1 = x1;
        if (i + 3 < n) {
            int s = g_col[beg + i + 3];
            a1 = g_al_s2[s];
            x1 = *(const ull*)(g_xW2 + (long)s * 64 + 2 * lane);
        }
        float e = aC0 + ald;
        e = fmaxf(e, 0.2f * e);
        float w = __expf(e);
        d += w;
        acc = fma2(pk2(w, w), xC0, acc);
        e = aC1 + ald;
        e = fmaxf(e, 0.2f * e);
        w = __expf(e);
        d += w;
        acc = fma2(pk2(w, w), xC1, acc);
    }
    if (i < n) {
        float e = a0 + ald;
        e = fmaxf(e, 0.2f * e);
        float w = __expf(e);
        d += w;
        acc = fma2(pk2(w, w), x0, acc);
    }
    float ax, ay; upk2(acc, ax, ay);
    float inv = 1.f / d;
    float ox = ax * inv + b2[2 * lane];
    float oy = ay * inv + b2[2 * lane + 1];
    ox = (ox > 0.f) ? ox : expm1f(ox);
    oy = (oy > 0.f) ? oy : expm1f(oy);
    *(float2*)(g_h2 + (long)node * 64 + 2 * lane) = make_float2(ox, oy);
}

// ---------------- fold lin_W (+bias) into mlp_W1 halves ----------------
__global__ void k_fold(const float* __restrict__ linW, const float* __restrict__ linb,
                       const float* __restrict__ mW1)
{
    int b = blockIdx.x;           // 129 blocks
    int c = threadIdx.x;          // 128 threads
    if (b < 128) {
        int i = b & 63;
        int off = (b >> 6) ? 64 : 0;
        float s = 0.f;
        for (int j = 0; j < 64; j++)
            s = fmaf(linW[i * 64 + j], mW1[(off + j) * 128 + c], s);
        ((b >> 6) ? g_Wlb : g_Wla)[i * 128 + c] = s;
    } else {
        float s0 = 0.f, s1 = 0.f;
        for (int j = 0; j < 64; j++) {
            s0 = fmaf(linb[j], mW1[j * 128 + c], s0);
            s1 = fmaf(linb[j], mW1[(64 + j) * 128 + c], s1);
        }
        g_bP[c] = s0;
        g_bQ[c] = s1;
    }
}

// ---------------- edge MLP + log_softmax (edge-parallel, 2-edge interleave) -------
__global__ void __launch_bounds__(256, 2)
k_edge(const int* __restrict__ ei, const float* __restrict__ ea,
       const float* __restrict__ mW1, const float* __restrict__ mb1,
       const float* __restrict__ mW2, const float* __restrict__ mb2,
       float* __restrict__ out)
{
    int lane = threadIdx.x & 31;
    int warp = (blockIdx.x * blockDim.x + threadIdx.x) >> 5;
    int nwarps = (gridDim.x * blockDim.x) >> 5;

    ull wc2[16][2];
#pragma unroll
    for (int k = 0; k < 16; k++) {
        ulonglong2 v = *(const ulonglong2*)(mW1 + (long)(128 + k) * 128 + 4 * lane);
        wc2[k][0] = v.x; wc2[k][1] = v.y;
    }
    float w2a[4], w2b[4];
#pragma unroll
    for (int u = 0; u < 4; u++) {
        int j = 4 * lane + u;
        w2a[u] = mW2[j * 2 + 0];
        w2b[u] = mW2[j * 2 + 1];
    }
    ull br2[2];
    {
        float4 b = *(const float4*)(mb1 + 4 * lane);
        br2[0] = pk2(b.x, b.y);
        br2[1] = pk2(b.z, b.w);
    }
    float b20 = mb2[0], b21 = mb2[1];

    for (int e = warp; e < NE; e += 2 * nwarps) {
        int e2 = e + nwarps;
        bool has2 = (e2 < NE);
        int eB = has2 ? e2 : e;

        int srcA = ei[e],  dstA = ei[NE + e];
        int srcB = ei[eB], dstB = ei[NE + eB];
        float ealA = (lane < 16) ? ea[(long)e * 16 + lane] : 0.f;
        float ealB = (lane < 16) ? ea[(long)eB * 16 + lane] : 0.f;
        ulonglong2 PA = *(const ulonglong2*)(g_P + (long)srcA * 128 + 4 * lane);
        ulonglong2 QA = *(const ulonglong2*)(g_Q + (long)dstA * 128 + 4 * lane);
        ulonglong2 PB = *(const ulonglong2*)(g_P + (long)srcB * 128 + 4 * lane);
        ulonglong2 QB = *(const ulonglong2*)(g_Q + (long)dstB * 128 + 4 * lane);

        ull hA0 = add2(add2(PA.x, QA.x), br2[0]);
        ull hA1 = add2(add2(PA.y, QA.y), br2[1]);
        ull hB0 = add2(add2(PB.x, QB.x), br2[0]);
        ull hB1 = add2(add2(PB.y, QB.y), br2[1]);
#pragma unroll
        for (int k = 0; k < 16; k++) {
            float ekA = __shfl_sync(0xffffffffu, ealA, k);
            float ekB = __shfl_sync(0xffffffffu, ealB, k);
            ull eA = pk2(ekA, ekA);
            ull eB2 = pk2(ekB, ekB);
            hA0 = fma2(eA, wc2[k][0], hA0);
            hA1 = fma2(eA, wc2[k][1], hA1);
            hB0 = fma2(eB2, wc2[k][0], hB0);
            hB1 = fma2(eB2, wc2[k][1], hB1);
        }
        float a0, a1, a2, a3, c0, c1, c2, c3;
        upk2(hA0, a0, a1); upk2(hA1, a2, a3);
        upk2(hB0, c0, c1); upk2(hB1, c2, c3);
        a0 = fmaxf(a0, 0.f); a1 = fmaxf(a1, 0.f); a2 = fmaxf(a2, 0.f); a3 = fmaxf(a3, 0.f);
        c0 = fmaxf(c0, 0.f); c1 = fmaxf(c1, 0.f); c2 = fmaxf(c2, 0.f); c3 = fmaxf(c3, 0.f);
        float sA0 = fmaf(a0, w2a[0], fmaf(a1, w2a[1], fmaf(a2, w2a[2], a3 * w2a[3])));
        float sA1 = fmaf(a0, w2b[0], fmaf(a1, w2b[1], fmaf(a2, w2b[2], a3 * w2b[3])));
        float sB0 = fmaf(c0, w2a[0], fmaf(c1, w2a[1], fmaf(c2, w2a[2], c3 * w2a[3])));
        float sB1 = fmaf(c0, w2b[0], fmaf(c1, w2b[1], fmaf(c2, w2b[2], c3 * w2b[3])));
#pragma unroll
        for (int off = 16; off >= 1; off >>= 1) {
            sA0 += __shfl_xor_sync(0xffffffffu, sA0, off);
            sA1 += __shfl_xor_sync(0xffffffffu, sA1, off);
            sB0 += __shfl_xor_sync(0xffffffffu, sB0, off);
            sB1 += __shfl_xor_sync(0xffffffffu, sB1, off);
        }
        if (lane == 0) {
            float o0 = sA0 + b20, o1 = sA1 + b21;
            float mx = fmaxf(o0, o1), mn = fminf(o0, o1);
            float l = mx + log1pf(expf(mn - mx));
            *(float2*)(out + (long)e * 2) = make_float2(o0 - l, o1 - l);
            if (has2) {
                float p0 = sB0 + b20, p1 = sB1 + b21;
                float mx2 = fmaxf(p0, p1), mn2 = fminf(p0, p1);
                float l2 = mx2 + log1pf(expf(mn2 - mx2));
                *(float2*)(out + (long)e2 * 2) = make_float2(p0 - l2, p1 - l2);
            }
        }
    }
}

// ---------------- host ----------------
extern "C" void kernel_launch(void* const* d_in, const int* in_sizes, int n_in,
                              void* d_out, int out_size)
{
    (void)in_sizes; (void)n_in; (void)out_size;
    const float* x    = (const float*)d_in[0];
    const int*   ei   = (const int*)d_in[1];
    const float* eatt = (const float*)d_in[2];
    const float* W1   = (const float*)d_in[3];
    const float* as1  = (const float*)d_in[4];
    const float* ad1  = (const float*)d_in[5];
    const float* b1   = (const float*)d_in[6];
    const float* W2   = (const float*)d_in[7];
    const float* as2  = (const float*)d_in[8];
    const float* ad2  = (const float*)d_in[9];
    const float* b2   = (const float*)d_in[10];
    const float* linW = (const float*)d_in[11];
    const float* linb = (const float*)d_in[12];
    const float* mW1  = (const float*)d_in[13];
    const float* mb1  = (const float*)d_in[14];
    const float* mW2  = (const float*)d_in[15];
    const float* mb2  = (const float*)d_in[16];
    float* out = (float*)d_out;

    void *p_xW1, *p_als1, *p_ald1, *p_h1, *p_xW2, *p_als2, *p_ald2, *p_h2;
    void *p_P, *p_Q, *p_Wla, *p_Wlb, *p_bP, *p_bQ;
    cudaGetSymbolAddress(&p_xW1, g_xW1);
    cudaGetSymbolAddress(&p_als1, g_al_s1);
    cudaGetSymbolAddress(&p_ald1, g_al_d1);
    cudaGetSymbolAddress(&p_h1, g_h1);
    cudaGetSymbolAddress(&p_xW2, g_xW2);
    cudaGetSymbolAddress(&p_als2, g_al_s2);
    cudaGetSymbolAddress(&p_ald2, g_al_d2);
    cudaGetSymbolAddress(&p_h2, g_h2);
    cudaGetSymbolAddress(&p_P, g_P);
    cudaGetSymbolAddress(&p_Q, g_Q);
    cudaGetSymbolAddress(&p_Wla, g_Wla);
    cudaGetSymbolAddress(&p_Wlb, g_Wlb);
    cudaGetSymbolAddress(&p_bP, g_bP);
    cudaGetSymbolAddress(&p_bQ, g_bQ);

    const int G128 = (NN + 127) / 128;            // 782 (BM=128 GEMM)
    const int WARP_BLOCKS = (NN + 7) / 8;         // 12500 (warp per node)
    const int EDGE_BLOCKS = (NE + 255) / 256;     // 6250

    // Side stream for the CSR chain (falls back to sequential stream 0 on failure).
    cudaStream_t s1 = 0;
    cudaEvent_t eFork = 0, eJoin = 0, eFork2 = 0, eJoin2 = 0;
    bool par = (cudaStreamCreateWithFlags(&s1, cudaStreamNonBlocking) == cudaSuccess);
    if (par) {
        par = (cudaEventCreateWithFlags(&eFork,  cudaEventDisableTiming) == cudaSuccess) &&
              (cudaEventCreateWithFlags(&eJoin,  cudaEventDisableTiming) == cudaSuccess) &&
              (cudaEventCreateWithFlags(&eFork2, cudaEventDisableTiming) == cudaSuccess) &&
              (cudaEventCreateWithFlags(&eJoin2, cudaEventDisableTiming) == cudaSuccess);
        if (!par) s1 = 0;
    }

    if (par) { cudaEventRecord(eFork, 0); cudaStreamWaitEvent(s1, eFork, 0); }

    // CSR chain on side stream (independent of GEMM1)
    k_zero<<<(NN + 255) / 256, 256, 0, s1>>>();
    k_hist<<<EDGE_BLOCKS, 256, 0, s1>>>(ei);
    k_scan1<<<(NN + 1023) / 1024, 256, 0, s1>>>();

    // GAT layer 1 projection + fused attention logits (profiled slot)
    k_gemm<128, 64, 4, 8><<<G128, 256>>>(x, W1, 64, nullptr, (float*)p_xW1, NN,
                                         as1, ad1, (float*)p_als1, (float*)p_ald1);

    k_scan2<<<1, 128, 0, s1>>>();
    k_scan3<<<(NN + 1 + 255) / 256, 256, 0, s1>>>();
    k_scatter<<<EDGE_BLOCKS, 256, 0, s1>>>(ei);
    k_fold<<<129, 128, 0, s1>>>(linW, linb, mW1);

    if (par) { cudaEventRecord(eJoin, s1); cudaStreamWaitEvent(0, eJoin, 0); }

    k_gat1<<<WARP_BLOCKS, 256>>>(b1);

    // GAT layer 2
    k_gemm<64, 64, 4, 1><<<G128, 256>>>((const float*)p_h1, W2, 64, nullptr,
                                        (float*)p_xW2, NN,
                                        as2, ad2, (float*)p_als2, (float*)p_ald2);
    k_gat2<<<WARP_BLOCKS, 256>>>(b2);

    // P/Q GEMMs: independent of each other -> run concurrently
    if (par) { cudaEventRecord(eFork2, 0); cudaStreamWaitEvent(s1, eFork2, 0); }
    k_gemm<64, 128, 8, 0><<<G128, 256, 0, s1>>>((const float*)p_h2, (const float*)p_Wlb, 128,
                                                (const float*)p_bQ, (float*)p_Q, NN,
                                                nullptr, nullptr, nullptr, nullptr);
    k_gemm<64, 128, 8, 0><<<G128, 256>>>((const float*)p_h2, (const float*)p_Wla, 128,
                                         (const float*)p_bP, (float*)p_P, NN,
                                         nullptr, nullptr, nullptr, nullptr);
    if (par) { cudaEventRecord(eJoin2, s1); cudaStreamWaitEvent(0, eJoin2, 0); }

    // edge MLP + log_softmax (ea and out fully streamed; P/Q random but L2-resident)
    k_edge<<<2368, 256>>>(ei, eatt, mW1, mb1, mW2, mb2, out);
}

// round 10
// speedup vs baseline: 2.2874x; 1.1660x over previous
#include <cuda_runtime.h>
#include <math.h>

#define NN 100000
#define NE 1600000

typedef unsigned long long ull;

// ---------------- f32x2 packed math (sm_100+; ptxas never emits these from C++) ----
__device__ __forceinline__ ull pk2(float lo, float hi) {
    ull r; asm("mov.b64 %0, {%1, %2};" : "=l"(r) : "f"(lo), "f"(hi)); return r;
}
__device__ __forceinline__ void upk2(ull v, float& lo, float& hi) {
    asm("mov.b64 {%0, %1}, %2;" : "=f"(lo), "=f"(hi) : "l"(v));
}
__device__ __forceinline__ ull fma2(ull a, ull b, ull c) {
    ull d; asm("fma.rn.f32x2 %0, %1, %2, %3;" : "=l"(d) : "l"(a), "l"(b), "l"(c)); return d;
}
__device__ __forceinline__ ull add2(ull a, ull b) {
    ull d; asm("add.rn.f32x2 %0, %1, %2;" : "=l"(d) : "l"(a), "l"(b)); return d;
}
__device__ __forceinline__ ull mul2(ull a, ull b) {
    ull d; asm("mul.rn.f32x2 %0, %1, %2;" : "=l"(d) : "l"(a), "l"(b)); return d;
}

// ---------------- scratch (device globals; no allocation allowed) ----------------
__device__ float g_xW1[NN * 64];
__device__ float g_al_s1[NN * 8];
__device__ float g_al_d1[NN * 8];
__device__ float g_h1[NN * 64];
__device__ float g_xW2[NN * 64];
__device__ float g_al_s2[NN];
__device__ float g_al_d2[NN];
__device__ float g_h2[NN * 64];
__device__ float g_P[NN * 128];
__device__ float g_Q[NN * 128];
__device__ float g_Wla[64 * 128];
__device__ float g_Wlb[64 * 128];
__device__ float g_bP[128];
__device__ float g_bQ[128];
__device__ int   g_deg[NN];
__device__ int   g_cursor[NN];
__device__ int   g_scantmp[NN];
__device__ int   g_rowptr[NN + 1];
__device__ int   g_bsum[128];
__device__ int   g_col[NE];

// ---------------- GEMM: C[nrows,BN] = A[nrows,K] @ B[K,BN] (+bias)
// BM=128, microtile 8 rows x TN cols, 256 threads, A-chunk register prefetch.
// ALH: 0 = plain, 8 = fused 8-head attention logits, 1 = fused 1-head logits
template <int K, int BN, int TN, int ALH>
__global__ void __launch_bounds__(256, TN == 8 ? 2 : 3)
k_gemm(const float* __restrict__ A, const float* __restrict__ B, int ldb,
       const float* __restrict__ bias, float* __restrict__ C, int nrows,
       const float* __restrict__ a_src, const float* __restrict__ a_dst,
       float* __restrict__ al_s, float* __restrict__ al_d)
{
    constexpr int BM = 128, KC = 16, PAD = 132;
    __shared__ __align__(16) float sB[K * BN];
    __shared__ __align__(16) float sA[KC * PAD];
    const int tid = threadIdx.x;
    const int tx = tid & 15, tyr = tid >> 4;
    const int rowBase = blockIdx.x * BM;

    for (int i = tid; i < K * BN; i += 256)
        sB[i] = B[(i / BN) * ldb + (i % BN)];

    ull accp[8][TN / 2];
#pragma unroll
    for (int i = 0; i < 8; i++)
#pragma unroll
        for (int j = 0; j < TN / 2; j++) accp[i][j] = pk2(0.f, 0.f);

    const int rL = tid & 127;
    const int k4 = (tid >> 7) * 8;
    const int gr = rowBase + rL;
    const bool rowOk = (gr < nrows);

    float4 pa0 = make_float4(0.f, 0.f, 0.f, 0.f);
    float4 pa1 = make_float4(0.f, 0.f, 0.f, 0.f);
    if (rowOk) {
        pa0 = *(const float4*)(A + (long)gr * K + k4);
        pa1 = *(const float4*)(A + (long)gr * K + k4 + 4);
    }
    sA[(k4 + 0) * PAD + rL] = pa0.x;
    sA[(k4 + 1) * PAD + rL] = pa0.y;
    sA[(k4 + 2) * PAD + rL] = pa0.z;
    sA[(k4 + 3) * PAD + rL] = pa0.w;
    sA[(k4 + 4) * PAD + rL] = pa1.x;
    sA[(k4 + 5) * PAD + rL] = pa1.y;
    sA[(k4 + 6) * PAD + rL] = pa1.z;
    sA[(k4 + 7) * PAD + rL] = pa1.w;
    __syncthreads();

    for (int kc = 0; kc < K; kc += KC) {
        const bool more = (kc + KC < K);
        if (more && rowOk) {
            pa0 = *(const float4*)(A + (long)gr * K + kc + KC + k4);
            pa1 = *(const float4*)(A + (long)gr * K + kc + KC + k4 + 4);
        }
#pragma unroll
        for (int kk = 0; kk < KC; kk++) {
            float4 a0 = *(const float4*)&sA[kk * PAD + 8 * tyr];
            float4 a1 = *(const float4*)&sA[kk * PAD + 8 * tyr + 4];
            ull bv[TN / 2];
            {
                ulonglong2 b2 = *(const ulonglong2*)&sB[(kc + kk) * BN + 4 * tx];
                bv[0] = b2.x; bv[1] = b2.y;
                if (TN == 8) {
                    ulonglong2 b3 = *(const ulonglong2*)&sB[(kc + kk) * BN + 64 + 4 * tx];
                    bv[2] = b3.x; bv[3] = b3.y;
                }
            }
            float av8[8] = {a0.x, a0.y, a0.z, a0.w, a1.x, a1.y, a1.z, a1.w};
#pragma unroll
            for (int i = 0; i < 8; i++) {
                ull ap = pk2(av8[i], av8[i]);
#pragma unroll
                for (int j = 0; j < TN / 2; j++)
                    accp[i][j] = fma2(ap, bv[j], accp[i][j]);
            }
        }
        if (more) {
            __syncthreads();
            sA[(k4 + 0) * PAD + rL] = pa0.x;
            sA[(k4 + 1) * PAD + rL] = pa0.y;
            sA[(k4 + 2) * PAD + rL] = pa0.z;
            sA[(k4 + 3) * PAD + rL] = pa0.w;
            sA[(k4 + 4) * PAD + rL] = pa1.x;
            sA[(k4 + 5) * PAD + rL] = pa1.y;
            sA[(k4 + 6) * PAD + rL] = pa1.z;
            sA[(k4 + 7) * PAD + rL] = pa1.w;
            __syncthreads();
        }
    }

    float acc[8][TN];
#pragma unroll
    for (int i = 0; i < 8; i++)
#pragma unroll
        for (int j = 0; j < TN / 2; j++)
            upk2(accp[i][j], acc[i][2 * j], acc[i][2 * j + 1]);

    float bb[TN];
#pragma unroll
    for (int j = 0; j < TN; j++) {
        int col = (j < 4) ? (4 * tx + j) : (64 + 4 * tx + (j - 4));
        bb[j] = bias ? bias[col] : 0.f;
    }
#pragma unroll
    for (int i = 0; i < 8; i++) {
        int r = rowBase + 8 * tyr + i;
        if (r < nrows) {
            float4 o;
            o.x = acc[i][0] + bb[0]; o.y = acc[i][1] + bb[1];
            o.z = acc[i][2] + bb[2]; o.w = acc[i][3] + bb[3];
            *(float4*)(C + (long)r * BN + 4 * tx) = o;
            if (TN == 8) {
                float4 o2;
                o2.x = acc[i][4] + bb[4]; o2.y = acc[i][5] + bb[5];
                o2.z = acc[i][6] + bb[6]; o2.w = acc[i][7] + bb[7];
                *(float4*)(C + (long)r * BN + 64 + 4 * tx) = o2;
            }
        }
    }

    if (ALH > 0) {
        float as4[4], ad4[4];
#pragma unroll
        for (int j = 0; j < 4; j++) {
            as4[j] = a_src[4 * tx + j];
            ad4[j] = a_dst[4 * tx + j];
        }
#pragma unroll
        for (int i = 0; i < 8; i++) {
            float ps = 0.f, pd = 0.f;
#pragma unroll
            for (int j = 0; j < 4; j++) {
                ps = fmaf(acc[i][j], as4[j], ps);
                pd = fmaf(acc[i][j], ad4[j], pd);
            }
            int r = rowBase + 8 * tyr + i;
            if (ALH == 8) {
                ps += __shfl_xor_sync(0xffffffffu, ps, 1);
                pd += __shfl_xor_sync(0xffffffffu, pd, 1);
                if (!(tx & 1) && r < nrows) {
                    al_s[(long)r * 8 + (tx >> 1)] = ps;
                    al_d[(long)r * 8 + (tx >> 1)] = pd;
                }
            } else {
#pragma unroll
                for (int off = 8; off >= 1; off >>= 1) {
                    ps += __shfl_xor_sync(0xffffffffu, ps, off);
                    pd += __shfl_xor_sync(0xffffffffu, pd, off);
                }
                if (tx == 0 && r < nrows) { al_s[r] = ps; al_d[r] = pd; }
            }
        }
    }
}

// ---------------- CSR build ----------------
__global__ void k_zero()
{
    int i = blockIdx.x * blockDim.x + threadIdx.x;
    if (i < NN) g_deg[i] = 0;
}
__global__ void k_hist(const int* __restrict__ ei)
{
    int e = blockIdx.x * blockDim.x + threadIdx.x;
    if (e < NE) atomicAdd(&g_deg[ei[NE + e]], 1);
}
__global__ void k_scan1()
{
    __shared__ int s[256];
    int tid = threadIdx.x;
    int base = blockIdx.x * 1024 + tid * 4;
    int v0 = (base + 0 < NN) ? g_deg[base + 0] : 0;
    int v1 = (base + 1 < NN) ? g_deg[base + 1] : 0;
    int v2 = (base + 2 < NN) ? g_deg[base + 2] : 0;
    int v3 = (base + 3 < NN) ? g_deg[base + 3] : 0;
    v1 += v0; v2 += v1; v3 += v2;
    int tot = v3;
    s[tid] = tot;
    __syncthreads();
    for (int off = 1; off < 256; off <<= 1) {
        int x = (tid >= off) ? s[tid - off] : 0;
        __syncthreads();
        s[tid] += x;
        __syncthreads();
    }
    int excl = s[tid] - tot;
    if (base + 0 < NN) g_scantmp[base + 0] = v0 + excl;
    if (base + 1 < NN) g_scantmp[base + 1] = v1 + excl;
    if (base + 2 < NN) g_scantmp[base + 2] = v2 + excl;
    if (base + 3 < NN) g_scantmp[base + 3] = v3 + excl;
    if (tid == 255) g_bsum[blockIdx.x] = s[255];
}
__global__ void k_scan2()
{
    __shared__ int s[128];
    int tid = threadIdx.x;
    int nb = (NN + 1023) / 1024;
    int v = (tid < nb) ? g_bsum[tid] : 0;
    s[tid] = v;
    __syncthreads();
    for (int off = 1; off < 128; off <<= 1) {
        int x = (tid >= off) ? s[tid - off] : 0;
        __syncthreads();
        s[tid] += x;
        __syncthreads();
    }
    if (tid < nb) g_bsum[tid] = s[tid] - v;  // exclusive
}
__global__ void k_scan3()
{
    int i = blockIdx.x * blockDim.x + threadIdx.x;
    if (i > NN) return;
    int v = (i == 0) ? 0 : (g_scantmp[i - 1] + g_bsum[(i - 1) >> 10]);
    g_rowptr[i] = v;
    if (i < NN) g_cursor[i] = v;
}
__global__ void k_scatter(const int* __restrict__ ei)
{
    int e = blockIdx.x * blockDim.x + threadIdx.x;
    if (e >= NE) return;
    int dst = ei[NE + e];
    int pos = atomicAdd(&g_cursor[dst], 1);
    g_col[pos] = ei[e];
}

// ---------------- GAT layer 1 (8 heads, depth-2 pipeline, dual accum chains) ------
__global__ void __launch_bounds__(256)
k_gat1(const float* __restrict__ b1)
{
    int node = (blockIdx.x * blockDim.x + threadIdx.x) >> 5;
    int lane = threadIdx.x & 31;
    if (node >= NN) return;
    int hl = lane >> 2;
    float ald = g_al_d1[(long)node * 8 + hl];

    // self-loop seeds chain 0
    float e0 = g_al_s1[(long)node * 8 + hl] + ald;
    e0 = fmaxf(e0, 0.2f * e0);
    float w0 = __expf(e0);
    float d0 = w0, d1 = 0.f;
    ull acc0 = mul2(pk2(w0, w0), *(const ull*)(g_xW1 + (long)node * 64 + 2 * lane));
    ull acc1 = pk2(0.f, 0.f);

    int beg = g_rowptr[node];
    int n = g_rowptr[node + 1] - beg;
    float a0 = 0.f, a1 = 0.f; ull x0 = 0, x1 = 0;
    if (n > 0) {
        int s = g_col[beg];
        a0 = g_al_s1[(long)s * 8 + hl];
        x0 = *(const ull*)(g_xW1 + (long)s * 64 + 2 * lane);
    }
    if (n > 1) {
        int s = g_col[beg + 1];
        a1 = g_al_s1[(long)s * 8 + hl];
        x1 = *(const ull*)(g_xW1 + (long)s * 64 + 2 * lane);
    }
    int i = 0;
    for (; i + 1 < n; i += 2) {
        float aC0 = a0; ull xC0 = x0;
        if (i + 2 < n) {
            int s = g_col[beg + i + 2];
            a0 = g_al_s1[(long)s * 8 + hl];
            x0 = *(const ull*)(g_xW1 + (long)s * 64 + 2 * lane);
        }
        float aC1 = a1; ull xC1 = x1;
        if (i + 3 < n) {
            int s = g_col[beg + i + 3];
            a1 = g_al_s1[(long)s * 8 + hl];
            x1 = *(const ull*)(g_xW1 + (long)s * 64 + 2 * lane);
        }
        float e = aC0 + ald;
        e = fmaxf(e, 0.2f * e);
        float w = __expf(e);
        d0 += w;
        acc0 = fma2(pk2(w, w), xC0, acc0);
        float e2 = aC1 + ald;
        e2 = fmaxf(e2, 0.2f * e2);
        float w2 = __expf(e2);
        d1 += w2;
        acc1 = fma2(pk2(w2, w2), xC1, acc1);
    }
    if (i < n) {
        float e = a0 + ald;
        e = fmaxf(e, 0.2f * e);
        float w = __expf(e);
        d0 += w;
        acc0 = fma2(pk2(w, w), x0, acc0);
    }
    float d = d0 + d1;
    ull acc = add2(acc0, acc1);
    float ax, ay; upk2(acc, ax, ay);
    float inv = 1.f / d;
    float ox = ax * inv + b1[2 * lane];
    float oy = ay * inv + b1[2 * lane + 1];
    ox = (ox > 0.f) ? ox : expm1f(ox);
    oy = (oy > 0.f) ? oy : expm1f(oy);
    *(float2*)(g_h1 + (long)node * 64 + 2 * lane) = make_float2(ox, oy);
}

// ---------------- GAT layer 2 (1 head, depth-2 pipeline, dual accum chains) -------
__global__ void __launch_bounds__(256)
k_gat2(const float* __restrict__ b2)
{
    int node = (blockIdx.x * blockDim.x + threadIdx.x) >> 5;
    int lane = threadIdx.x & 31;
    if (node >= NN) return;
    float ald = g_al_d2[node];
    float e0 = g_al_s2[node] + ald;
    e0 = fmaxf(e0, 0.2f * e0);
    float w0 = __expf(e0);
    float d0 = w0, d1 = 0.f;
    ull acc0 = mul2(pk2(w0, w0), *(const ull*)(g_xW2 + (long)node * 64 + 2 * lane));
    ull acc1 = pk2(0.f, 0.f);

    int beg = g_rowptr[node];
    int n = g_rowptr[node + 1] - beg;
    float a0 = 0.f, a1 = 0.f; ull x0 = 0, x1 = 0;
    if (n > 0) {
        int s = g_col[beg];
        a0 = g_al_s2[s];
        x0 = *(const ull*)(g_xW2 + (long)s * 64 + 2 * lane);
    }
    if (n > 1) {
        int s = g_col[beg + 1];
        a1 = g_al_s2[s];
        x1 = *(const ull*)(g_xW2 + (long)s * 64 + 2 * lane);
    }
    int i = 0;
    for (; i + 1 < n; i += 2) {
        float aC0 = a0; ull xC0 = x0;
        if (i + 2 < n) {
            int s = g_col[beg + i + 2];
            a0 = g_al_s2[s];
            x0 = *(const ull*)(g_xW2 + (long)s * 64 + 2 * lane);
        }
        float aC1 = a1; ull xC1 = x1;
        if (i + 3 < n) {
            int s = g_col[beg + i + 3];
            a1 = g_al_s2[s];
            x1 = *(const ull*)(g_xW2 + (long)s * 64 + 2 * lane);
        }
        float e = aC0 + ald;
        e = fmaxf(e, 0.2f * e);
        float w = __expf(e);
        d0 += w;
        acc0 = fma2(pk2(w, w), xC0, acc0);
        float e2 = aC1 + ald;
        e2 = fmaxf(e2, 0.2f * e2);
        float w2 = __expf(e2);
        d1 += w2;
        acc1 = fma2(pk2(w2, w2), xC1, acc1);
    }
    if (i < n) {
        float e = a0 + ald;
        e = fmaxf(e, 0.2f * e);
        float w = __expf(e);
        d0 += w;
        acc0 = fma2(pk2(w, w), x0, acc0);
    }
    float d = d0 + d1;
    ull acc = add2(acc0, acc1);
    float ax, ay; upk2(acc, ax, ay);
    float inv = 1.f / d;
    float ox = ax * inv + b2[2 * lane];
    float oy = ay * inv + b2[2 * lane + 1];
    ox = (ox > 0.f) ? ox : expm1f(ox);
    oy = (oy > 0.f) ? oy : expm1f(oy);
    *(float2*)(g_h2 + (long)node * 64 + 2 * lane) = make_float2(ox, oy);
}

// ---------------- fold lin_W (+bias) into mlp_W1 halves ----------------
__global__ void k_fold(const float* __restrict__ linW, const float* __restrict__ linb,
                       const float* __restrict__ mW1)
{
    int b = blockIdx.x;           // 129 blocks
    int c = threadIdx.x;          // 128 threads
    if (b < 128) {
        int i = b & 63;
        int off = (b >> 6) ? 64 : 0;
        float s = 0.f;
        for (int j = 0; j < 64; j++)
            s = fmaf(linW[i * 64 + j], mW1[(off + j) * 128 + c], s);
        ((b >> 6) ? g_Wlb : g_Wla)[i * 128 + c] = s;
    } else {
        float s0 = 0.f, s1 = 0.f;
        for (int j = 0; j < 64; j++) {
            s0 = fmaf(linb[j], mW1[j * 128 + c], s0);
            s1 = fmaf(linb[j], mW1[(64 + j) * 128 + c], s1);
        }
        g_bP[c] = s0;
        g_bQ[c] = s1;
    }
}

// ---------------- edge MLP + log_softmax (pair-pipelined: data depth-1, idx depth-2)
__global__ void __launch_bounds__(256, 2)
k_edge(const int* __restrict__ ei, const float* __restrict__ ea,
       const float* __restrict__ mW1, const float* __restrict__ mb1,
       const float* __restrict__ mW2, const float* __restrict__ mb2,
       float* __restrict__ out)
{
    const int lane = threadIdx.x & 31;
    const long warp = ((long)blockIdx.x * blockDim.x + threadIdx.x) >> 5;
    const long nwarps = ((long)gridDim.x * blockDim.x) >> 5;
    const long stride = 2 * nwarps;
    const int laneK = lane & 15;

    ull wc2[16][2];
#pragma unroll
    for (int k = 0; k < 16; k++) {
        ulonglong2 v = *(const ulonglong2*)(mW1 + (long)(128 + k) * 128 + 4 * lane);
        wc2[k][0] = v.x; wc2[k][1] = v.y;
    }
    float w2a[4], w2b[4];
#pragma unroll
    for (int u = 0; u < 4; u++) {
        int j = 4 * lane + u;
        w2a[u] = mW2[j * 2 + 0];
        w2b[u] = mW2[j * 2 + 1];
    }
    ull br2[2];
    {
        float4 b = *(const float4*)(mb1 + 4 * lane);
        br2[0] = pk2(b.x, b.y);
        br2[1] = pk2(b.z, b.w);
    }
    const float b20 = mb2[0], b21 = mb2[1];

    long e = warp;
    if (e >= NE) return;

    // slot 0: indices + ea + P/Q data for current pair
    int sA0, dA0, sB0, dB0; float ea0;
    {
        long e2 = e + nwarps; long eB = (e2 < NE) ? e2 : e;
        sA0 = ei[e]; dA0 = ei[NE + e];
        sB0 = ei[eB]; dB0 = ei[NE + eB];
        long ee = (lane < 16) ? e : eB;
        ea0 = ea[ee * 16 + laneK];
    }
    ulonglong2 PA0 = *(const ulonglong2*)(g_P + (long)sA0 * 128 + 4 * lane);
    ulonglong2 QA0 = *(const ulonglong2*)(g_Q + (long)dA0 * 128 + 4 * lane);
    ulonglong2 PB0 = *(const ulonglong2*)(g_P + (long)sB0 * 128 + 4 * lane);
    ulonglong2 QB0 = *(const ulonglong2*)(g_Q + (long)dB0 * 128 + 4 * lane);

    // slot 1: indices + ea for next pair (clamped so loads are always valid)
    int sA1, dA1, sB1, dB1; float ea1;
    {
        long en = e + stride; long ec = (en < NE) ? en : e;
        long e2 = ec + nwarps; long eB = (e2 < NE) ? e2 : ec;
        sA1 = ei[ec]; dA1 = ei[NE + ec];
        sB1 = ei[eB]; dB1 = ei[NE + eB];
        long ee = (lane < 16) ? ec : eB;
        ea1 = ea[ee * 16 + laneK];
    }

    for (;;) {
        // issue next pair's P/Q loads now (indices resolved one iteration ago)
        ulonglong2 PA1 = *(const ulonglong2*)(g_P + (long)sA1 * 128 + 4 * lane);
        ulonglong2 QA1 = *(const ulonglong2*)(g_Q + (long)dA1 * 128 + 4 * lane);
        ulonglong2 PB1 = *(const ulonglong2*)(g_P + (long)sB1 * 128 + 4 * lane);
        ulonglong2 QB1 = *(const ulonglong2*)(g_Q + (long)dB1 * 128 + 4 * lane);

        // prefetch indices + ea for the pair after next (clamped)
        int sA2, dA2, sB2, dB2; float ea2;
        {
            long en = e + 2 * stride; long ec = (en < NE) ? en : e;
            long e2 = ec + nwarps; long eB = (e2 < NE) ? e2 : ec;
            sA2 = ei[ec]; dA2 = ei[NE + ec];
            sB2 = ei[eB]; dB2 = ei[NE + eB];
            long ee = (lane < 16) ? ec : eB;
            ea2 = ea[ee * 16 + laneK];
        }

        // compute current pair
        ull hA0 = add2(add2(PA0.x, QA0.x), br2[0]);
        ull hA1 = add2(add2(PA0.y, QA0.y), br2[1]);
        ull hB0 = add2(add2(PB0.x, QB0.x), br2[0]);
        ull hB1 = add2(add2(PB0.y, QB0.y), br2[1]);
#pragma unroll
        for (int k = 0; k < 16; k++) {
            float ekA = __shfl_sync(0xffffffffu, ea0, k);
            float ekB = __shfl_sync(0xffffffffu, ea0, 16 + k);
            ull eAp = pk2(ekA, ekA);
            ull eBp = pk2(ekB, ekB);
            hA0 = fma2(eAp, wc2[k][0], hA0);
            hA1 = fma2(eAp, wc2[k][1], hA1);
            hB0 = fma2(eBp, wc2[k][0], hB0);
            hB1 = fma2(eBp, wc2[k][1], hB1);
        }
        float a0, a1, a2, a3, c0, c1, c2, c3;
        upk2(hA0, a0, a1); upk2(hA1, a2, a3);
        upk2(hB0, c0, c1); upk2(hB1, c2, c3);
        a0 = fmaxf(a0, 0.f); a1 = fmaxf(a1, 0.f); a2 = fmaxf(a2, 0.f); a3 = fmaxf(a3, 0.f);
        c0 = fmaxf(c0, 0.f); c1 = fmaxf(c1, 0.f); c2 = fmaxf(c2, 0.f); c3 = fmaxf(c3, 0.f);
        float sA = fmaf(a0, w2a[0], fmaf(a1, w2a[1], fmaf(a2, w2a[2], a3 * w2a[3])));
        float sAy = fmaf(a0, w2b[0], fmaf(a1, w2b[1], fmaf(a2, w2b[2], a3 * w2b[3])));
        float sB = fmaf(c0, w2a[0], fmaf(c1, w2a[1], fmaf(c2, w2a[2], c3 * w2a[3])));
        float sBy = fmaf(c0, w2b[0], fmaf(c1, w2b[1], fmaf(c2, w2b[2], c3 * w2b[3])));
#pragma unroll
        for (int off = 16; off >= 1; off >>= 1) {
            sA  += __shfl_xor_sync(0xffffffffu, sA, off);
            sAy += __shfl_xor_sync(0xffffffffu, sAy, off);
            sB  += __shfl_xor_sync(0xffffffffu, sB, off);
            sBy += __shfl_xor_sync(0xffffffffu, sBy, off);
        }
        if (lane == 0) {
            float o0 = sA + b20, o1 = sAy + b21;
            float mx = fmaxf(o0, o1), mn = fminf(o0, o1);
            float l = mx + log1pf(expf(mn - mx));
            *(float2*)(out + e * 2) = make_float2(o0 - l, o1 - l);
            long e2 = e + nwarps;
            if (e2 < NE) {
                float p0 = sB + b20, p1 = sBy + b21;
                float mx2 = fmaxf(p0, p1), mn2 = fminf(p0, p1);
                float l2 = mx2 + log1pf(expf(mn2 - mx2));
                *(float2*)(out + e2 * 2) = make_float2(p0 - l2, p1 - l2);
            }
        }

        // advance
        long en = e + stride;
        if (en >= NE) break;
        e = en;
        PA0 = PA1; QA0 = QA1; PB0 = PB1; QB0 = QB1; ea0 = ea1;
        sA1 = sA2; dA1 = dA2; sB1 = sB2; dB1 = dB2; ea1 = ea2;
    }
}

// ---------------- host ----------------
extern "C" void kernel_launch(void* const* d_in, const int* in_sizes, int n_in,
                              void* d_out, int out_size)
{
    (void)in_sizes; (void)n_in; (void)out_size;
    const float* x    = (const float*)d_in[0];
    const int*   ei   = (const int*)d_in[1];
    const float* eatt = (const float*)d_in[2];
    const float* W1   = (const float*)d_in[3];
    const float* as1  = (const float*)d_in[4];
    const float* ad1  = (const float*)d_in[5];
    const float* b1   = (const float*)d_in[6];
    const float* W2   = (const float*)d_in[7];
    const float* as2  = (const float*)d_in[8];
    const float* ad2  = (const float*)d_in[9];
    const float* b2   = (const float*)d_in[10];
    const float* linW = (const float*)d_in[11];
    const float* linb = (const float*)d_in[12];
    const float* mW1  = (const float*)d_in[13];
    const float* mb1  = (const float*)d_in[14];
    const float* mW2  = (const float*)d_in[15];
    const float* mb2  = (const float*)d_in[16];
    float* out = (float*)d_out;

    void *p_xW1, *p_als1, *p_ald1, *p_h1, *p_xW2, *p_als2, *p_ald2, *p_h2;
    void *p_P, *p_Q, *p_Wla, *p_Wlb, *p_bP, *p_bQ;
    cudaGetSymbolAddress(&p_xW1, g_xW1);
    cudaGetSymbolAddress(&p_als1, g_al_s1);
    cudaGetSymbolAddress(&p_ald1, g_al_d1);
    cudaGetSymbolAddress(&p_h1, g_h1);
    cudaGetSymbolAddress(&p_xW2, g_xW2);
    cudaGetSymbolAddress(&p_als2, g_al_s2);
    cudaGetSymbolAddress(&p_ald2, g_al_d2);
    cudaGetSymbolAddress(&p_h2, g_h2);
    cudaGetSymbolAddress(&p_P, g_P);
    cudaGetSymbolAddress(&p_Q, g_Q);
    cudaGetSymbolAddress(&p_Wla, g_Wla);
    cudaGetSymbolAddress(&p_Wlb, g_Wlb);
    cudaGetSymbolAddress(&p_bP, g_bP);
    cudaGetSymbolAddress(&p_bQ, g_bQ);

    const int G128 = (NN + 127) / 128;            // 782 (BM=128 GEMM)
    const int WARP_BLOCKS = (NN + 7) / 8;         // 12500 (warp per node)
    const int EDGE_BLOCKS = (NE + 255) / 256;     // 6250

    cudaStream_t s1 = 0;
    cudaEvent_t eFork = 0, eJoin = 0, eFork2 = 0, eJoin2 = 0;
    bool par = (cudaStreamCreateWithFlags(&s1, cudaStreamNonBlocking) == cudaSuccess);
    if (par) {
        par = (cudaEventCreateWithFlags(&eFork,  cudaEventDisableTiming) == cudaSuccess) &&
              (cudaEventCreateWithFlags(&eJoin,  cudaEventDisableTiming) == cudaSuccess) &&
              (cudaEventCreateWithFlags(&eFork2, cudaEventDisableTiming) == cudaSuccess) &&
              (cudaEventCreateWithFlags(&eJoin2, cudaEventDisableTiming) == cudaSuccess);
        if (!par) s1 = 0;
    }

    if (par) { cudaEventRecord(eFork, 0); cudaStreamWaitEvent(s1, eFork, 0); }

    // CSR chain on side stream (independent of GEMM1)
    k_zero<<<(NN + 255) / 256, 256, 0, s1>>>();
    k_hist<<<EDGE_BLOCKS, 256, 0, s1>>>(ei);
    k_scan1<<<(NN + 1023) / 1024, 256, 0, s1>>>();

    // GAT layer 1 projection + fused attention logits (profiled slot)
    k_gemm<128, 64, 4, 8><<<G128, 256>>>(x, W1, 64, nullptr, (float*)p_xW1, NN,
                                         as1, ad1, (float*)p_als1, (float*)p_ald1);

    k_scan2<<<1, 128, 0, s1>>>();
    k_scan3<<<(NN + 1 + 255) / 256, 256, 0, s1>>>();
    k_scatter<<<EDGE_BLOCKS, 256, 0, s1>>>(ei);
    k_fold<<<129, 128, 0, s1>>>(linW, linb, mW1);

    if (par) { cudaEventRecord(eJoin, s1); cudaStreamWaitEvent(0, eJoin, 0); }

    k_gat1<<<WARP_BLOCKS, 256>>>(b1);

    // GAT layer 2
    k_gemm<64, 64, 4, 1><<<G128, 256>>>((const float*)p_h1, W2, 64, nullptr,
                                        (float*)p_xW2, NN,
                                        as2, ad2, (float*)p_als2, (float*)p_ald2);
    k_gat2<<<WARP_BLOCKS, 256>>>(b2);

    // P/Q GEMMs: independent of each other -> run concurrently
    if (par) { cudaEventRecord(eFork2, 0); cudaStreamWaitEvent(s1, eFork2, 0); }
    k_gemm<64, 128, 8, 0><<<G128, 256, 0, s1>>>((const float*)p_h2, (const float*)p_Wlb, 128,
                                                (const float*)p_bQ, (float*)p_Q, NN,
                                                nullptr, nullptr, nullptr, nullptr);
    k_gemm<64, 128, 8, 0><<<G128, 256>>>((const float*)p_h2, (const float*)p_Wla, 128,
                                         (const float*)p_bP, (float*)p_P, NN,
                                         nullptr, nullptr, nullptr, nullptr);
    if (par) { cudaEventRecord(eJoin2, s1); cudaStreamWaitEvent(0, eJoin2, 0); }

    // edge MLP + log_softmax (pipelined; ea/out streamed, P/Q L2-resident gathers)
    k_edge<<<2368, 256>>>(ei, eatt, mW1, mb1, mW2, mb2, out);
}